// round 13
// baseline (speedup 1.0000x reference)
#include <cuda_runtime.h>
#include <cuda_fp16.h>
#include <math.h>
#include <stdint.h>

#define NN 50000
#define NE 200000
#define XLD 516      // xc row stride (floats)
#define AP  1600     // fp16 A/B row stride (multiple of 32)
#define NBLK 196     // scan blocks (ceil(NN/256))
#define ESTG 1024    // edge window staged in smem per 64-node group

typedef unsigned long long u64;

// ---------------- scratch ----------------
__device__ float g_xc[(size_t)NN * XLD];
__device__ __align__(16) __half g_ah[(size_t)NN * AP];
__device__ __align__(16) __half g_wh[(size_t)512 * AP];
__device__ int   g_cnt[NN];
__device__ int   g_bsum[NBLK];
__device__ int   g_rowptr[NN + 1];
__device__ int   g_cursor[NN];
__device__ int   g_src[NE];
__device__ __align__(16) float g_ea[(size_t)NE * 8];   // padded to 8 for LDG.128
__device__ int   g_is64;
__device__ int   g_arrive;

// ---------------- helpers ----------------
__device__ __forceinline__ uint32_t su32(const void* p) {
    uint32_t a;
    asm("{ .reg .u64 t; cvta.to.shared.u64 t, %1; cvt.u32.u64 %0, t; }" : "=r"(a) : "l"(p));
    return a;
}
__device__ __forceinline__ u64 pk2(float lo, float hi) {
    u64 r;
    asm("mov.b64 %0, {%1, %2};" : "=l"(r) : "f"(lo), "f"(hi));
    return r;
}
__device__ __forceinline__ void upk2(float& lo, float& hi, u64 v) {
    asm("mov.b64 {%0, %1}, %2;" : "=f"(lo), "=f"(hi) : "l"(v));
}
__device__ __forceinline__ u64 fma2(u64 a, u64 b, u64 c) {
    asm("fma.rn.f32x2 %0, %1, %2, %0;" : "+l"(c) : "l"(a), "l"(b));
    return c;
}
__device__ __forceinline__ void ldm4(uint32_t* r, uint32_t addr) {
    asm volatile("ldmatrix.sync.aligned.m8n8.x4.shared.b16 {%0,%1,%2,%3}, [%4];"
                 : "=r"(r[0]), "=r"(r[1]), "=r"(r[2]), "=r"(r[3]) : "r"(addr));
}
__device__ __forceinline__ void mma16816(float* d, const uint32_t* a, const uint32_t* b) {
    asm volatile(
        "mma.sync.aligned.m16n8k16.row.col.f32.f16.f16.f32 "
        "{%0,%1,%2,%3}, {%4,%5,%6,%7}, {%8,%9}, {%0,%1,%2,%3};"
        : "+f"(d[0]), "+f"(d[1]), "+f"(d[2]), "+f"(d[3])
        : "r"(a[0]), "r"(a[1]), "r"(a[2]), "r"(a[3]), "r"(b[0]), "r"(b[1]));
}
__device__ __forceinline__ void cpa16(uint32_t dst, const void* src) {
    asm volatile("cp.async.cg.shared.global [%0], [%1], 16;" :: "r"(dst), "l"(src));
}
__device__ __forceinline__ void cp_commit() {
    asm volatile("cp.async.commit_group;" ::: "memory");
}
template <int N>
__device__ __forceinline__ void cp_wait() {
    asm volatile("cp.async.wait_group %0;" :: "n"(N) : "memory");
}
__device__ __forceinline__ float ftanh(float x) {
    float e = __expf(2.0f * x);
    return 1.0f - __fdividef(2.0f, e + 1.0f);
}

__device__ __forceinline__ int eload(const void* ei, int pos) {
    if (g_is64) return (int)((const long long*)ei)[pos];
    return ((const int*)ei)[pos];
}

// ---------------- (1) zero counters + detect edge_index dtype ----------------
__global__ void k_zero_detect(const int* ei32) {
    int i = blockIdx.x * blockDim.x + threadIdx.x;
    if (i < NN) g_cnt[i] = 0;
    if (i == 0) {
        g_arrive = 0;
        int z = 1;
        for (int k = 0; k < 64; k++)
            if (ei32[2 * k + 1] != 0) { z = 0; break; }
        g_is64 = z;
    }
}

// ---------------- (2) histogram of dst ----------------
__global__ void k_hist(const void* ei) {
    int e = blockIdx.x * blockDim.x + threadIdx.x;
    if (e < NE) atomicAdd(&g_cnt[eload(ei, NE + e)], 1);
}

// ---------------- (3) block sums + last-block scan of block sums ----------------
__global__ void k_scan12() {
    __shared__ int sm[256];
    __shared__ int lastFlag;
    int i = blockIdx.x * 256 + threadIdx.x;
    sm[threadIdx.x] = (i < NN) ? g_cnt[i] : 0;
    __syncthreads();
    for (int off = 128; off; off >>= 1) {
        if (threadIdx.x < off) sm[threadIdx.x] += sm[threadIdx.x + off];
        __syncthreads();
    }
    if (threadIdx.x == 0) {
        g_bsum[blockIdx.x] = sm[0];
        __threadfence();
        int t = atomicAdd(&g_arrive, 1);
        lastFlag = (t == gridDim.x - 1);
    }
    __syncthreads();
    if (lastFlag) {
        int t = threadIdx.x;
        int v = (t < NBLK) ? g_bsum[t] : 0;
        sm[t] = v;
        __syncthreads();
        for (int off = 1; off < 256; off <<= 1) {
            int u = (t >= off) ? sm[t - off] : 0;
            __syncthreads();
            sm[t] += u;
            __syncthreads();
        }
        if (t < NBLK) g_bsum[t] = sm[t] - v;
        if (t == NBLK - 1) g_rowptr[NN] = sm[t];
    }
}

// ---------------- (4) per-block exclusive scan -> rowptr, cursor ----------------
__global__ void k_scan3() {
    __shared__ int sm[256];
    int i = blockIdx.x * 256 + threadIdx.x;
    int v = (i < NN) ? g_cnt[i] : 0;
    sm[threadIdx.x] = v;
    __syncthreads();
    for (int off = 1; off < 256; off <<= 1) {
        int u = (threadIdx.x >= off) ? sm[threadIdx.x - off] : 0;
        __syncthreads();
        sm[threadIdx.x] += u;
        __syncthreads();
    }
    if (i < NN) {
        int ex = sm[threadIdx.x] - v + g_bsum[blockIdx.x];
        g_rowptr[i] = ex;
        g_cursor[i] = ex;
    }
}

// ---------------- (5) scatter edges to CSR + prep xc rows ----------------
__global__ void k_scatter_prep(const void* ei, const float* __restrict__ ea,
                               const float* __restrict__ x, const float* __restrict__ sdf,
                               const float* __restrict__ nat) {
    int idx = blockIdx.x * blockDim.x + threadIdx.x;
    if (idx < NE) {
        int e = idx;
        int d = eload(ei, NE + e);
        int s = eload(ei, e);
        int pos = atomicAdd(&g_cursor[d], 1);
        g_src[pos] = s;
        float4 v0 = make_float4(ea[e * 6 + 0], ea[e * 6 + 1], ea[e * 6 + 2], ea[e * 6 + 3]);
        float4 v1 = make_float4(ea[e * 6 + 4], ea[e * 6 + 5], 0.f, 0.f);
        *(float4*)(g_ea + (size_t)pos * 8)     = v0;
        *(float4*)(g_ea + (size_t)pos * 8 + 4) = v1;
    }
    if (idx < NN) {
        float* r = &g_xc[(size_t)idx * XLD];
#pragma unroll
        for (int c = 0; c < 5; c++) r[c] = x[idx * 5 + c];
        r[5] = sdf[idx];
        r[6] = nat[idx];
    }
}

// ---------------- xc concat fixups ----------------
__global__ void k_setcol(int col, const float* __restrict__ src) {
    int n = blockIdx.x * blockDim.x + threadIdx.x;
    if (n < NN) g_xc[(size_t)n * XLD + col] = src[n];
}
__global__ void k_copyfy(const float* __restrict__ fy) {
    int idx = blockIdx.x * blockDim.x + threadIdx.x;
    if (idx >= NN * 3) return;
    int n = idx / 3, c = idx - n * 3;
    g_xc[(size_t)n * XLD + c] = fy[idx];
}

// ---------------- weight prep: fp16, permuted k = h*in_c + i ----------------
__global__ void k_permw_f16(const float* __restrict__ wout, int in_c, int Kpad) {
    int K = 3 * in_c;
    int idx = blockIdx.x * blockDim.x + threadIdx.x;
    if (idx >= 512 * Kpad) return;
    int o = idx / Kpad, k = idx - o * Kpad;
    float v = 0.f;
    if (k < K) {
        int h = k / in_c, i = k - h * in_c;
        v = wout[(size_t)o * K + i * 3 + h];
    }
    g_wh[(size_t)o * AP + k] = __float2half_rn(v);
}

// ---------------- (6) fused scaling + gather + segment-sum -> fp16 ----------------
// FFMA2 (fma.rn.f32x2) packed channel pairs: thread owns channels (2t, 2t+1);
// tail channels 512.. handled scalar by threads 0..3. Full fp32 precision.
__global__ void __launch_bounds__(256, 2) k_aggr(int in_c, int kpad,
                                                 const float* __restrict__ win,
                                                 const float* __restrict__ bin) {
    __shared__ float s_ea[ESTG * 8];
    __shared__ int   s_src[ESTG];
    const int tid = threadIdx.x;
    const int c0 = 2 * tid;                 // pair channels c0, c0+1
    const bool pv0 = (c0 < in_c);
    const bool pv1 = (c0 + 1 < in_c);
    const int ct = 512 + tid;               // tail channel
    const bool tv = (ct < in_c);

    // packed pair weights/biases: wp[h*6+a] = (w[c0,h,a], w[c0+1,h,a])
    u64 wp[18], bp[3];
#pragma unroll
    for (int h = 0; h < 3; h++) {
#pragma unroll
        for (int a = 0; a < 6; a++) {
            float lo = pv0 ? win[c0 * 18 + h * 6 + a] : 0.f;
            float hi = pv1 ? win[(c0 + 1) * 18 + h * 6 + a] : 0.f;
            wp[h * 6 + a] = pk2(lo, hi);
        }
        float bl = pv0 ? bin[c0 * 3 + h] : 0.f;
        float bh = pv1 ? bin[(c0 + 1) * 3 + h] : 0.f;
        bp[h] = pk2(bl, bh);
    }
    // scalar tail weights/biases
    float wt[18], bt[3];
#pragma unroll
    for (int t = 0; t < 18; t++) wt[t] = tv ? win[ct * 18 + t] : 0.f;
#pragma unroll
    for (int h = 0; h < 3; h++) bt[h] = tv ? bin[ct * 3 + h] : 0.f;

    const int R = 3 * in_c, pad = kpad - R;
    const int n0 = blockIdx.x * 64;
    const int nend = (n0 + 64 < NN) ? n0 + 64 : NN;
    const int e0 = g_rowptr[n0], e1 = g_rowptr[nend];

    u64 A0 = 0ULL, A1 = 0ULL, A2 = 0ULL;
    float at0 = 0.f, at1 = 0.f, at2 = 0.f;
    int n = n0;
    int ws = e0;
    while (true) {
        int wc = e1 - ws;
        if (wc > ESTG) wc = ESTG;
        if (wc < 0) wc = 0;
        __syncthreads();
        for (int t = tid; t < wc * 8; t += 256) s_ea[t] = g_ea[(size_t)ws * 8 + t];
        for (int t = tid; t < wc; t += 256) s_src[t] = g_src[ws + t];
        __syncthreads();
        const int wend = ws + wc;

        while (n < nend) {
            const int rs = g_rowptr[n], re = g_rowptr[n + 1];
            const int js = (rs > ws) ? rs : ws;
            const int je = (re < wend) ? re : wend;
            for (int j = js; j < je; j++) {
                const int lj = j - ws;
                const int s = s_src[lj];
                const float2 xv = *(const float2*)&g_xc[(size_t)s * XLD + c0];
                const float4 ef0 = *(const float4*)&s_ea[lj * 8];
                const float2 ef1 = *(const float2*)&s_ea[lj * 8 + 4];
                const float ev[6] = {ef0.x, ef0.y, ef0.z, ef0.w, ef1.x, ef1.y};
                u64 ep[6];
#pragma unroll
                for (int a = 0; a < 6; a++) ep[a] = pk2(ev[a], ev[a]);

                u64 s0 = bp[0], s1 = bp[1], s2 = bp[2];
#pragma unroll
                for (int a = 0; a < 6; a++) {
                    s0 = fma2(ep[a], wp[a],      s0);
                    s1 = fma2(ep[a], wp[6 + a],  s1);
                    s2 = fma2(ep[a], wp[12 + a], s2);
                }
                const u64 xp = pk2(xv.x, xv.y);
                float l, h;
                upk2(l, h, s0);
                A0 = fma2(pk2(fmaxf(l, 0.f), fmaxf(h, 0.f)), xp, A0);
                upk2(l, h, s1);
                A1 = fma2(pk2(fmaxf(l, 0.f), fmaxf(h, 0.f)), xp, A1);
                upk2(l, h, s2);
                A2 = fma2(pk2(fmaxf(l, 0.f), fmaxf(h, 0.f)), xp, A2);

                if (tv) {
                    const float xt = __ldg(&g_xc[(size_t)s * XLD + ct]);
                    float t0 = bt[0], t1 = bt[1], t2 = bt[2];
#pragma unroll
                    for (int a = 0; a < 6; a++) {
                        float e = ev[a];
                        t0 = fmaf(e, wt[a],      t0);
                        t1 = fmaf(e, wt[6 + a],  t1);
                        t2 = fmaf(e, wt[12 + a], t2);
                    }
                    at0 = fmaf(fmaxf(t0, 0.f), xt, at0);
                    at1 = fmaf(fmaxf(t1, 0.f), xt, at1);
                    at2 = fmaf(fmaxf(t2, 0.f), xt, at2);
                }
            }
            if (re <= wend) {
                const size_t rb = (size_t)n * AP;
                float l, h;
                upk2(l, h, A0);
                if (pv0) g_ah[rb + c0] = __float2half_rn(l);
                if (pv1) g_ah[rb + c0 + 1] = __float2half_rn(h);
                upk2(l, h, A1);
                if (pv0) g_ah[rb + in_c + c0] = __float2half_rn(l);
                if (pv1) g_ah[rb + in_c + c0 + 1] = __float2half_rn(h);
                upk2(l, h, A2);
                if (pv0) g_ah[rb + 2 * in_c + c0] = __float2half_rn(l);
                if (pv1) g_ah[rb + 2 * in_c + c0 + 1] = __float2half_rn(h);
                if (tv) {
                    g_ah[rb + ct]            = __float2half_rn(at0);
                    g_ah[rb + in_c + ct]     = __float2half_rn(at1);
                    g_ah[rb + 2 * in_c + ct] = __float2half_rn(at2);
                }
                for (int p = tid; p < pad; p += 256)
                    g_ah[rb + R + p] = __float2half_rn(0.f);
                A0 = 0ULL; A1 = 0ULL; A2 = 0ULL;
                at0 = 0.f; at1 = 0.f; at2 = 0.f;
                n++;
            } else {
                break;   // node straddles window; carry acc to next window
            }
        }
        if (n >= nend) break;
        ws += ESTG;
    }
}

// ---------------- fp16 HMMA GEMM, 128x128 tile, cp.async 2-stage ----------------
#define SROW  80
#define SA    0
#define SB    (128 * SROW)        // 10240
#define STGSZ (2 * 128 * SROW)    // 20480
#define SMTOT (2 * STGSZ)         // 40960

__device__ __forceinline__ void gemm_issue(uint32_t st, int c, int c16,
                                           int ra0, int ra1, int rb0, int rb1,
                                           int r0, int r1) {
    size_t ka = (size_t)c * 32 + c16 * 8;
    uint32_t d0 = st + r0 * SROW + c16 * 16;
    uint32_t d1 = st + r1 * SROW + c16 * 16;
    cpa16(d0 + SA, g_ah + (size_t)ra0 * AP + ka);
    cpa16(d1 + SA, g_ah + (size_t)ra1 * AP + ka);
    cpa16(d0 + SB, g_wh + (size_t)rb0 * AP + ka);
    cpa16(d1 + SB, g_wh + (size_t)rb1 * AP + ka);
    cp_commit();
}

__global__ void __launch_bounds__(256, 2) k_gemm_mma(int M, int NC,
                                                     const float* __restrict__ bias,
                                                     int coloff) {
    extern __shared__ __align__(16) char dsm[];
    const int tid = threadIdx.x;
    const int wid = tid >> 5;
    const int lane = tid & 31;
    const int m0 = blockIdx.y * 128;
    const int n0 = blockIdx.x * 128;
    const uint32_t sb = su32(dsm);

    const int wm = (wid >> 2) * 64;
    const int wn = (wid & 3) * 32;

    float acc[4][4][4];
#pragma unroll
    for (int mt = 0; mt < 4; mt++)
#pragma unroll
        for (int nt = 0; nt < 4; nt++)
#pragma unroll
            for (int q = 0; q < 4; q++) acc[mt][nt][q] = 0.f;

    const int r0 = tid >> 2, c16 = tid & 3;
    const int r1 = r0 + 64;
    int ra0 = m0 + r0; if (ra0 >= M) ra0 = M - 1;
    int ra1 = m0 + r1; if (ra1 >= M) ra1 = M - 1;
    const int rb0 = n0 + r0, rb1 = n0 + r1;

    gemm_issue(sb, 0, c16, ra0, ra1, rb0, rb1, r0, r1);

    for (int c = 0; c < NC; c++) {
        const int b = c & 1;
        if (c + 1 < NC) {
            gemm_issue(sb + ((c + 1) & 1) * STGSZ, c + 1, c16, ra0, ra1, rb0, rb1, r0, r1);
            cp_wait<1>();
        } else {
            cp_wait<0>();
        }
        __syncthreads();

        const uint32_t st = sb + b * STGSZ;
#pragma unroll
        for (int s = 0; s < 2; s++) {
            uint32_t ah[4][4];
#pragma unroll
            for (int mt = 0; mt < 4; mt++) {
                uint32_t row = wm + mt * 16 + (lane & 15);
                uint32_t ad = st + SA + row * SROW + s * 32 + (lane >> 4) * 16;
                ldm4(ah[mt], ad);
            }
            uint32_t bh[4][2];
#pragma unroll
            for (int p = 0; p < 2; p++) {
                uint32_t row = wn + p * 16 + (lane & 7) + (lane >> 4) * 8;
                uint32_t bd = st + SB + row * SROW + s * 32 + ((lane >> 3) & 1) * 16;
                uint32_t r[4];
                ldm4(r, bd);
                bh[2 * p][0] = r[0]; bh[2 * p][1] = r[1];
                bh[2 * p + 1][0] = r[2]; bh[2 * p + 1][1] = r[3];
            }
#pragma unroll
            for (int mt = 0; mt < 4; mt++)
#pragma unroll
                for (int nt = 0; nt < 4; nt++)
                    mma16816(acc[mt][nt], ah[mt], bh[nt]);
        }
        __syncthreads();
    }

#pragma unroll
    for (int mt = 0; mt < 4; mt++) {
        int gm0 = m0 + wm + mt * 16 + (lane >> 2);
        int gm1 = gm0 + 8;
#pragma unroll
        for (int nt = 0; nt < 4; nt++) {
            int cn = n0 + wn + nt * 8 + (lane & 3) * 2;
            float b0 = bias[cn], b1 = bias[cn + 1];
            if (gm0 < M) {
                float* p = &g_xc[(size_t)gm0 * XLD + coloff + cn];
                p[0] = fmaxf(ftanh(acc[mt][nt][0] + b0), 0.f);
                p[1] = fmaxf(ftanh(acc[mt][nt][1] + b1), 0.f);
            }
            if (gm1 < M) {
                float* p = &g_xc[(size_t)gm1 * XLD + coloff + cn];
                p[0] = fmaxf(ftanh(acc[mt][nt][2] + b0), 0.f);
                p[1] = fmaxf(ftanh(acc[mt][nt][3] + b1), 0.f);
            }
        }
    }
}

// ---------------- last layer (out_c = 3): warp per node, fp32, tanh only ----------------
__global__ void __launch_bounds__(256) k_gemm_small(int in_c, const float* __restrict__ wout,
                                                    const float* __restrict__ bias,
                                                    float* __restrict__ out) {
    int node = blockIdx.x * 8 + (threadIdx.x >> 5);
    int lane = threadIdx.x & 31;
    if (node >= NN) return;
    const int K = 3 * in_c;
    const __half* hi = g_ah + (size_t)node * AP;
    float c0 = 0.f, c1 = 0.f, c2 = 0.f;
    for (int h = 0; h < 3; h++) {
        for (int i = lane; i < in_c; i += 32) {
            int k = h * in_c + i;
            float a = __half2float(hi[k]);
            int wi = i * 3 + h;
            c0 = fmaf(a, wout[0 * (size_t)K + wi], c0);
            c1 = fmaf(a, wout[1 * (size_t)K + wi], c1);
            c2 = fmaf(a, wout[2 * (size_t)K + wi], c2);
        }
    }
#pragma unroll
    for (int o = 16; o; o >>= 1) {
        c0 += __shfl_down_sync(0xffffffffu, c0, o);
        c1 += __shfl_down_sync(0xffffffffu, c1, o);
        c2 += __shfl_down_sync(0xffffffffu, c2, o);
    }
    if (lane == 0) {
        out[(size_t)node * 3 + 0] = tanhf(c0 + bias[0]);
        out[(size_t)node * 3 + 1] = tanhf(c1 + bias[1]);
        out[(size_t)node * 3 + 2] = tanhf(c2 + bias[2]);
    }
}

// ---------------- launch ----------------
extern "C" void kernel_launch(void* const* d_in, const int* in_sizes, int n_in,
                              void* d_out, int out_size) {
    (void)in_sizes; (void)n_in; (void)out_size;
    const float* x   = (const float*)d_in[0];
    const float* sdf = (const float*)d_in[1];
    const float* nat = (const float*)d_in[2];
    const float* ea  = (const float*)d_in[3];
    const float* fy  = (const float*)d_in[4];
    const void*  ei  = d_in[5];
    const float* win[6];  const float* bin[6];
    const float* wout[6]; const float* bout[6];
    for (int l = 0; l < 6; l++) {
        win[l]  = (const float*)d_in[6 + 4 * l];
        bin[l]  = (const float*)d_in[7 + 4 * l];
        wout[l] = (const float*)d_in[8 + 4 * l];
        bout[l] = (const float*)d_in[9 + 4 * l];
    }
    float* out = (float*)d_out;

    static const int IN_C[6] = {7, 513, 513, 516, 513, 513};
    static const int COFF[6] = {0, 0, 3, 0, 0, 0};

    cudaFuncSetAttribute(k_gemm_mma, cudaFuncAttributeMaxDynamicSharedMemorySize, SMTOT);

    const int TB = 256;
    k_zero_detect<<<(NN + TB - 1) / TB, TB>>>((const int*)ei);
    k_hist<<<(NE + TB - 1) / TB, TB>>>(ei);
    k_scan12<<<NBLK, 256>>>();
    k_scan3<<<NBLK, 256>>>();
    k_scatter_prep<<<(NE + TB - 1) / TB, TB>>>(ei, ea, x, sdf, nat);

    for (int l = 0; l < 6; l++) {
        const int inc = IN_C[l];
        const int K = 3 * inc;
        const int NC = (K + 31) / 32;
        const int Kpad = NC * 32;

        k_aggr<<<(NN + 63) / 64, 256>>>(inc, Kpad, win[l], bin[l]);
        if (l < 5) {
            k_permw_f16<<<(512 * Kpad + TB - 1) / TB, TB>>>(wout[l], inc, Kpad);
            dim3 grid(4, (NN + 127) / 128);
            k_gemm_mma<<<grid, 256, SMTOT>>>(NN, NC, bout[l], COFF[l]);
        } else {
            k_gemm_small<<<(NN + 7) / 8, 256>>>(inc, wout[l], bout[l], out);
        }
        if (l == 0) {
            k_setcol<<<(NN + TB - 1) / TB, TB>>>(512, nat);
        } else if (l == 2) {
            k_copyfy<<<(NN * 3 + TB - 1) / TB, TB>>>(fy);
            k_setcol<<<(NN + TB - 1) / TB, TB>>>(515, nat);
        } else if (l == 3) {
            k_setcol<<<(NN + TB - 1) / TB, TB>>>(512, nat);
        }
    }
}

// round 14
// speedup vs baseline: 1.0298x; 1.0298x over previous
#include <cuda_runtime.h>
#include <cuda_fp16.h>
#include <math.h>
#include <stdint.h>

#define NN 50000
#define NE 200000
#define XLD 516      // xc row stride (floats)
#define AP  1600     // fp16 A/B row stride (multiple of 32)
#define NBLK 196     // scan blocks (ceil(NN/256))
#define ESTG 1024    // edge window staged in smem per 64-node group

// ---------------- scratch ----------------
__device__ float g_xc[(size_t)NN * XLD];
__device__ __align__(16) __half g_ah[(size_t)NN * AP];
__device__ __align__(16) __half g_wh[(size_t)512 * AP];
__device__ int   g_cnt[NN];
__device__ int   g_bsum[NBLK];
__device__ int   g_rowptr[NN + 1];
__device__ int   g_cursor[NN];
__device__ int   g_src[NE];
__device__ __align__(16) float g_ea[(size_t)NE * 8];   // padded to 8 for LDG.128
__device__ int   g_is64;
__device__ int   g_arrive;

// ---------------- helpers ----------------
__device__ __forceinline__ uint32_t su32(const void* p) {
    uint32_t a;
    asm("{ .reg .u64 t; cvta.to.shared.u64 t, %1; cvt.u32.u64 %0, t; }" : "=r"(a) : "l"(p));
    return a;
}
__device__ __forceinline__ void ldm4(uint32_t* r, uint32_t addr) {
    asm volatile("ldmatrix.sync.aligned.m8n8.x4.shared.b16 {%0,%1,%2,%3}, [%4];"
                 : "=r"(r[0]), "=r"(r[1]), "=r"(r[2]), "=r"(r[3]) : "r"(addr));
}
__device__ __forceinline__ void mma16816(float* d, const uint32_t* a, const uint32_t* b) {
    asm volatile(
        "mma.sync.aligned.m16n8k16.row.col.f32.f16.f16.f32 "
        "{%0,%1,%2,%3}, {%4,%5,%6,%7}, {%8,%9}, {%0,%1,%2,%3};"
        : "+f"(d[0]), "+f"(d[1]), "+f"(d[2]), "+f"(d[3])
        : "r"(a[0]), "r"(a[1]), "r"(a[2]), "r"(a[3]), "r"(b[0]), "r"(b[1]));
}
__device__ __forceinline__ void cpa16(uint32_t dst, const void* src) {
    asm volatile("cp.async.cg.shared.global [%0], [%1], 16;" :: "r"(dst), "l"(src));
}
__device__ __forceinline__ void cp_commit() {
    asm volatile("cp.async.commit_group;" ::: "memory");
}
template <int N>
__device__ __forceinline__ void cp_wait() {
    asm volatile("cp.async.wait_group %0;" :: "n"(N) : "memory");
}
__device__ __forceinline__ float ftanh(float x) {
    float e = __expf(2.0f * x);
    return 1.0f - __fdividef(2.0f, e + 1.0f);
}

__device__ __forceinline__ int eload(const void* ei, int pos) {
    if (g_is64) return (int)((const long long*)ei)[pos];
    return ((const int*)ei)[pos];
}

// ---------------- (1) zero counters + detect edge_index dtype ----------------
__global__ void k_zero_detect(const int* ei32) {
    int i = blockIdx.x * blockDim.x + threadIdx.x;
    if (i < NN) g_cnt[i] = 0;
    if (i == 0) {
        g_arrive = 0;
        int z = 1;
        for (int k = 0; k < 64; k++)
            if (ei32[2 * k + 1] != 0) { z = 0; break; }
        g_is64 = z;
    }
}

// ---------------- (2) histogram of dst ----------------
__global__ void k_hist(const void* ei) {
    int e = blockIdx.x * blockDim.x + threadIdx.x;
    if (e < NE) atomicAdd(&g_cnt[eload(ei, NE + e)], 1);
}

// ---------------- (3) block sums + last-block scan of block sums ----------------
__global__ void k_scan12() {
    __shared__ int sm[256];
    __shared__ int lastFlag;
    int i = blockIdx.x * 256 + threadIdx.x;
    sm[threadIdx.x] = (i < NN) ? g_cnt[i] : 0;
    __syncthreads();
    for (int off = 128; off; off >>= 1) {
        if (threadIdx.x < off) sm[threadIdx.x] += sm[threadIdx.x + off];
        __syncthreads();
    }
    if (threadIdx.x == 0) {
        g_bsum[blockIdx.x] = sm[0];
        __threadfence();
        int t = atomicAdd(&g_arrive, 1);
        lastFlag = (t == gridDim.x - 1);
    }
    __syncthreads();
    if (lastFlag) {
        int t = threadIdx.x;
        int v = (t < NBLK) ? g_bsum[t] : 0;
        sm[t] = v;
        __syncthreads();
        for (int off = 1; off < 256; off <<= 1) {
            int u = (t >= off) ? sm[t - off] : 0;
            __syncthreads();
            sm[t] += u;
            __syncthreads();
        }
        if (t < NBLK) g_bsum[t] = sm[t] - v;
        if (t == NBLK - 1) g_rowptr[NN] = sm[t];
    }
}

// ---------------- (4) per-block exclusive scan -> rowptr, cursor ----------------
__global__ void k_scan3() {
    __shared__ int sm[256];
    int i = blockIdx.x * 256 + threadIdx.x;
    int v = (i < NN) ? g_cnt[i] : 0;
    sm[threadIdx.x] = v;
    __syncthreads();
    for (int off = 1; off < 256; off <<= 1) {
        int u = (threadIdx.x >= off) ? sm[threadIdx.x - off] : 0;
        __syncthreads();
        sm[threadIdx.x] += u;
        __syncthreads();
    }
    if (i < NN) {
        int ex = sm[threadIdx.x] - v + g_bsum[blockIdx.x];
        g_rowptr[i] = ex;
        g_cursor[i] = ex;
    }
}

// ---------------- (5) scatter edges to CSR + prep xc rows ----------------
__global__ void k_scatter_prep(const void* ei, const float* __restrict__ ea,
                               const float* __restrict__ x, const float* __restrict__ sdf,
                               const float* __restrict__ nat) {
    int idx = blockIdx.x * blockDim.x + threadIdx.x;
    if (idx < NE) {
        int e = idx;
        int d = eload(ei, NE + e);
        int s = eload(ei, e);
        int pos = atomicAdd(&g_cursor[d], 1);
        g_src[pos] = s;
        float4 v0 = make_float4(ea[e * 6 + 0], ea[e * 6 + 1], ea[e * 6 + 2], ea[e * 6 + 3]);
        float4 v1 = make_float4(ea[e * 6 + 4], ea[e * 6 + 5], 0.f, 0.f);
        *(float4*)(g_ea + (size_t)pos * 8)     = v0;
        *(float4*)(g_ea + (size_t)pos * 8 + 4) = v1;
    }
    if (idx < NN) {
        float* r = &g_xc[(size_t)idx * XLD];
#pragma unroll
        for (int c = 0; c < 5; c++) r[c] = x[idx * 5 + c];
        r[5] = sdf[idx];
        r[6] = nat[idx];
    }
}

// ---------------- xc concat fixups ----------------
__global__ void k_setcol(int col, const float* __restrict__ src) {
    int n = blockIdx.x * blockDim.x + threadIdx.x;
    if (n < NN) g_xc[(size_t)n * XLD + col] = src[n];
}
__global__ void k_copyfy(const float* __restrict__ fy) {
    int idx = blockIdx.x * blockDim.x + threadIdx.x;
    if (idx >= NN * 3) return;
    int n = idx / 3, c = idx - n * 3;
    g_xc[(size_t)n * XLD + c] = fy[idx];
}

// ---------------- weight prep: fp16, permuted k = h*in_c + i ----------------
__global__ void k_permw_f16(const float* __restrict__ wout, int in_c, int Kpad) {
    int K = 3 * in_c;
    int idx = blockIdx.x * blockDim.x + threadIdx.x;
    if (idx >= 512 * Kpad) return;
    int o = idx / Kpad, k = idx - o * Kpad;
    float v = 0.f;
    if (k < K) {
        int h = k / in_c, i = k - h * in_c;
        v = wout[(size_t)o * K + i * 3 + h];
    }
    g_wh[(size_t)o * AP + k] = __float2half_rn(v);
}

// ---------------- (6) fused scaling + gather + segment-sum -> fp16 ----------------
// R12 structure (group-level windows, scalar FMA, register weights) + one-edge-deep
// xv gather prefetch to overlap L2 gather latency with the 72-FMA block.
__global__ void __launch_bounds__(256, 2) k_aggr(int in_c, int kpad,
                                                 const float* __restrict__ win,
                                                 const float* __restrict__ bin) {
    __shared__ float s_ea[ESTG * 8];
    __shared__ int   s_src[ESTG];
    const int tid = threadIdx.x;
    const int i0 = tid, i1 = tid + 256, i2 = tid + 512;
    const bool v1 = (i1 < in_c), v2 = (i2 < in_c);

    // hoist per-channel weights/biases into registers (zeros for invalid sets)
    float w0[18], w1[18], w2[18];
#pragma unroll
    for (int t = 0; t < 18; t++) {
        w0[t] = (i0 < in_c) ? win[i0 * 18 + t] : 0.f;
        w1[t] = v1 ? win[i1 * 18 + t] : 0.f;
        w2[t] = v2 ? win[i2 * 18 + t] : 0.f;
    }
    float b0[3], b1[3], b2[3];
#pragma unroll
    for (int h = 0; h < 3; h++) {
        b0[h] = (i0 < in_c) ? bin[i0 * 3 + h] : 0.f;
        b1[h] = v1 ? bin[i1 * 3 + h] : 0.f;
        b2[h] = v2 ? bin[i2 * 3 + h] : 0.f;
    }

    const int R = 3 * in_c, pad = kpad - R;
    const int n0 = blockIdx.x * 64;
    const int nend = (n0 + 64 < NN) ? n0 + 64 : NN;
    const int e0 = g_rowptr[n0], e1 = g_rowptr[nend];

    float a0[3] = {0.f, 0.f, 0.f}, a1[3] = {0.f, 0.f, 0.f}, a2[3] = {0.f, 0.f, 0.f};
    int n = n0;
    int ws = e0;
    while (true) {
        int wc = e1 - ws;
        if (wc > ESTG) wc = ESTG;
        if (wc < 0) wc = 0;
        __syncthreads();
        for (int t = tid; t < wc * 8; t += 256) s_ea[t] = g_ea[(size_t)ws * 8 + t];
        for (int t = tid; t < wc; t += 256) s_src[t] = g_src[ws + t];
        __syncthreads();
        const int wend = ws + wc;

        while (n < nend) {
            const int rs = g_rowptr[n], re = g_rowptr[n + 1];
            const int js = (rs > ws) ? rs : ws;
            const int je = (re < wend) ? re : wend;

            // prefetch edge js's gathers
            float pxv0 = 0.f, pxv1 = 0.f, pxv2 = 0.f;
            if (js < je) {
                const int s = s_src[js - ws];
                pxv0 = __ldg(&g_xc[(size_t)s * XLD + i0]);
                pxv1 = v1 ? __ldg(&g_xc[(size_t)s * XLD + i1]) : 0.f;
                pxv2 = v2 ? __ldg(&g_xc[(size_t)s * XLD + i2]) : 0.f;
            }
            for (int j = js; j < je; j++) {
                const int lj = j - ws;
                const float xv0 = pxv0, xv1 = pxv1, xv2 = pxv2;
                const float4 ef0 = *(const float4*)&s_ea[lj * 8];
                const float2 ef1 = *(const float2*)&s_ea[lj * 8 + 4];
                // issue next edge's gathers before the FMA block
                if (j + 1 < je) {
                    const int s = s_src[lj + 1];
                    pxv0 = __ldg(&g_xc[(size_t)s * XLD + i0]);
                    pxv1 = v1 ? __ldg(&g_xc[(size_t)s * XLD + i1]) : 0.f;
                    pxv2 = v2 ? __ldg(&g_xc[(size_t)s * XLD + i2]) : 0.f;
                }
                const float ev[6] = {ef0.x, ef0.y, ef0.z, ef0.w, ef1.x, ef1.y};
                {
                    float s0 = b0[0], s1 = b0[1], s2 = b0[2];
#pragma unroll
                    for (int a = 0; a < 6; a++) {
                        float e = ev[a];
                        s0 = fmaf(e, w0[a], s0);
                        s1 = fmaf(e, w0[6 + a], s1);
                        s2 = fmaf(e, w0[12 + a], s2);
                    }
                    a0[0] = fmaf(fmaxf(s0, 0.f), xv0, a0[0]);
                    a0[1] = fmaf(fmaxf(s1, 0.f), xv0, a0[1]);
                    a0[2] = fmaf(fmaxf(s2, 0.f), xv0, a0[2]);
                }
                {
                    float s0 = b1[0], s1 = b1[1], s2 = b1[2];
#pragma unroll
                    for (int a = 0; a < 6; a++) {
                        float e = ev[a];
                        s0 = fmaf(e, w1[a], s0);
                        s1 = fmaf(e, w1[6 + a], s1);
                        s2 = fmaf(e, w1[12 + a], s2);
                    }
                    a1[0] = fmaf(fmaxf(s0, 0.f), xv1, a1[0]);
                    a1[1] = fmaf(fmaxf(s1, 0.f), xv1, a1[1]);
                    a1[2] = fmaf(fmaxf(s2, 0.f), xv1, a1[2]);
                }
                {
                    float s0 = b2[0], s1 = b2[1], s2 = b2[2];
#pragma unroll
                    for (int a = 0; a < 6; a++) {
                        float e = ev[a];
                        s0 = fmaf(e, w2[a], s0);
                        s1 = fmaf(e, w2[6 + a], s1);
                        s2 = fmaf(e, w2[12 + a], s2);
                    }
                    a2[0] = fmaf(fmaxf(s0, 0.f), xv2, a2[0]);
                    a2[1] = fmaf(fmaxf(s1, 0.f), xv2, a2[1]);
                    a2[2] = fmaf(fmaxf(s2, 0.f), xv2, a2[2]);
                }
            }
            if (re <= wend) {
                const size_t rb = (size_t)n * AP;
                if (i0 < in_c) {
                    g_ah[rb + i0]            = __float2half_rn(a0[0]);
                    g_ah[rb + in_c + i0]     = __float2half_rn(a0[1]);
                    g_ah[rb + 2 * in_c + i0] = __float2half_rn(a0[2]);
                }
                if (v1) {
                    g_ah[rb + i1]            = __float2half_rn(a1[0]);
                    g_ah[rb + in_c + i1]     = __float2half_rn(a1[1]);
                    g_ah[rb + 2 * in_c + i1] = __float2half_rn(a1[2]);
                }
                if (v2) {
                    g_ah[rb + i2]            = __float2half_rn(a2[0]);
                    g_ah[rb + in_c + i2]     = __float2half_rn(a2[1]);
                    g_ah[rb + 2 * in_c + i2] = __float2half_rn(a2[2]);
                }
                for (int p = tid; p < pad; p += 256)
                    g_ah[rb + R + p] = __float2half_rn(0.f);
#pragma unroll
                for (int q = 0; q < 3; q++) { a0[q] = 0.f; a1[q] = 0.f; a2[q] = 0.f; }
                n++;
            } else {
                break;   // node straddles window; carry acc to next window
            }
        }
        if (n >= nend) break;
        ws += ESTG;
    }
}

// ---------------- fp16 HMMA GEMM, 128x128 tile, cp.async 2-stage ----------------
#define SROW  80
#define SA    0
#define SB    (128 * SROW)        // 10240
#define STGSZ (2 * 128 * SROW)    // 20480
#define SMTOT (2 * STGSZ)         // 40960

__device__ __forceinline__ void gemm_issue(uint32_t st, int c, int c16,
                                           int ra0, int ra1, int rb0, int rb1,
                                           int r0, int r1) {
    size_t ka = (size_t)c * 32 + c16 * 8;
    uint32_t d0 = st + r0 * SROW + c16 * 16;
    uint32_t d1 = st + r1 * SROW + c16 * 16;
    cpa16(d0 + SA, g_ah + (size_t)ra0 * AP + ka);
    cpa16(d1 + SA, g_ah + (size_t)ra1 * AP + ka);
    cpa16(d0 + SB, g_wh + (size_t)rb0 * AP + ka);
    cpa16(d1 + SB, g_wh + (size_t)rb1 * AP + ka);
    cp_commit();
}

__global__ void __launch_bounds__(256, 2) k_gemm_mma(int M, int NC,
                                                     const float* __restrict__ bias,
                                                     int coloff) {
    extern __shared__ __align__(16) char dsm[];
    const int tid = threadIdx.x;
    const int wid = tid >> 5;
    const int lane = tid & 31;
    const int m0 = blockIdx.y * 128;
    const int n0 = blockIdx.x * 128;
    const uint32_t sb = su32(dsm);

    const int wm = (wid >> 2) * 64;
    const int wn = (wid & 3) * 32;

    float acc[4][4][4];
#pragma unroll
    for (int mt = 0; mt < 4; mt++)
#pragma unroll
        for (int nt = 0; nt < 4; nt++)
#pragma unroll
            for (int q = 0; q < 4; q++) acc[mt][nt][q] = 0.f;

    const int r0 = tid >> 2, c16 = tid & 3;
    const int r1 = r0 + 64;
    int ra0 = m0 + r0; if (ra0 >= M) ra0 = M - 1;
    int ra1 = m0 + r1; if (ra1 >= M) ra1 = M - 1;
    const int rb0 = n0 + r0, rb1 = n0 + r1;

    gemm_issue(sb, 0, c16, ra0, ra1, rb0, rb1, r0, r1);

    for (int c = 0; c < NC; c++) {
        const int b = c & 1;
        if (c + 1 < NC) {
            gemm_issue(sb + ((c + 1) & 1) * STGSZ, c + 1, c16, ra0, ra1, rb0, rb1, r0, r1);
            cp_wait<1>();
        } else {
            cp_wait<0>();
        }
        __syncthreads();

        const uint32_t st = sb + b * STGSZ;
#pragma unroll
        for (int s = 0; s < 2; s++) {
            uint32_t ah[4][4];
#pragma unroll
            for (int mt = 0; mt < 4; mt++) {
                uint32_t row = wm + mt * 16 + (lane & 15);
                uint32_t ad = st + SA + row * SROW + s * 32 + (lane >> 4) * 16;
                ldm4(ah[mt], ad);
            }
            uint32_t bh[4][2];
#pragma unroll
            for (int p = 0; p < 2; p++) {
                uint32_t row = wn + p * 16 + (lane & 7) + (lane >> 4) * 8;
                uint32_t bd = st + SB + row * SROW + s * 32 + ((lane >> 3) & 1) * 16;
                uint32_t r[4];
                ldm4(r, bd);
                bh[2 * p][0] = r[0]; bh[2 * p][1] = r[1];
                bh[2 * p + 1][0] = r[2]; bh[2 * p + 1][1] = r[3];
            }
#pragma unroll
            for (int mt = 0; mt < 4; mt++)
#pragma unroll
                for (int nt = 0; nt < 4; nt++)
                    mma16816(acc[mt][nt], ah[mt], bh[nt]);
        }
        __syncthreads();
    }

#pragma unroll
    for (int mt = 0; mt < 4; mt++) {
        int gm0 = m0 + wm + mt * 16 + (lane >> 2);
        int gm1 = gm0 + 8;
#pragma unroll
        for (int nt = 0; nt < 4; nt++) {
            int cn = n0 + wn + nt * 8 + (lane & 3) * 2;
            float b0 = bias[cn], b1 = bias[cn + 1];
            if (gm0 < M) {
                float* p = &g_xc[(size_t)gm0 * XLD + coloff + cn];
                p[0] = fmaxf(ftanh(acc[mt][nt][0] + b0), 0.f);
                p[1] = fmaxf(ftanh(acc[mt][nt][1] + b1), 0.f);
            }
            if (gm1 < M) {
                float* p = &g_xc[(size_t)gm1 * XLD + coloff + cn];
                p[0] = fmaxf(ftanh(acc[mt][nt][2] + b0), 0.f);
                p[1] = fmaxf(ftanh(acc[mt][nt][3] + b1), 0.f);
            }
        }
    }
}

// ---------------- last layer (out_c = 3): warp per node, fp32, tanh only ----------------
__global__ void __launch_bounds__(256) k_gemm_small(int in_c, const float* __restrict__ wout,
                                                    const float* __restrict__ bias,
                                                    float* __restrict__ out) {
    int node = blockIdx.x * 8 + (threadIdx.x >> 5);
    int lane = threadIdx.x & 31;
    if (node >= NN) return;
    const int K = 3 * in_c;
    const __half* hi = g_ah + (size_t)node * AP;
    float c0 = 0.f, c1 = 0.f, c2 = 0.f;
    for (int h = 0; h < 3; h++) {
        for (int i = lane; i < in_c; i += 32) {
            int k = h * in_c + i;
            float a = __half2float(hi[k]);
            int wi = i * 3 + h;
            c0 = fmaf(a, wout[0 * (size_t)K + wi], c0);
            c1 = fmaf(a, wout[1 * (size_t)K + wi], c1);
            c2 = fmaf(a, wout[2 * (size_t)K + wi], c2);
        }
    }
#pragma unroll
    for (int o = 16; o; o >>= 1) {
        c0 += __shfl_down_sync(0xffffffffu, c0, o);
        c1 += __shfl_down_sync(0xffffffffu, c1, o);
        c2 += __shfl_down_sync(0xffffffffu, c2, o);
    }
    if (lane == 0) {
        out[(size_t)node * 3 + 0] = tanhf(c0 + bias[0]);
        out[(size_t)node * 3 + 1] = tanhf(c1 + bias[1]);
        out[(size_t)node * 3 + 2] = tanhf(c2 + bias[2]);
    }
}

// ---------------- launch ----------------
extern "C" void kernel_launch(void* const* d_in, const int* in_sizes, int n_in,
                              void* d_out, int out_size) {
    (void)in_sizes; (void)n_in; (void)out_size;
    const float* x   = (const float*)d_in[0];
    const float* sdf = (const float*)d_in[1];
    const float* nat = (const float*)d_in[2];
    const float* ea  = (const float*)d_in[3];
    const float* fy  = (const float*)d_in[4];
    const void*  ei  = d_in[5];
    const float* win[6];  const float* bin[6];
    const float* wout[6]; const float* bout[6];
    for (int l = 0; l < 6; l++) {
        win[l]  = (const float*)d_in[6 + 4 * l];
        bin[l]  = (const float*)d_in[7 + 4 * l];
        wout[l] = (const float*)d_in[8 + 4 * l];
        bout[l] = (const float*)d_in[9 + 4 * l];
    }
    float* out = (float*)d_out;

    static const int IN_C[6] = {7, 513, 513, 516, 513, 513};
    static const int COFF[6] = {0, 0, 3, 0, 0, 0};

    cudaFuncSetAttribute(k_gemm_mma, cudaFuncAttributeMaxDynamicSharedMemorySize, SMTOT);

    const int TB = 256;
    k_zero_detect<<<(NN + TB - 1) / TB, TB>>>((const int*)ei);
    k_hist<<<(NE + TB - 1) / TB, TB>>>(ei);
    k_scan12<<<NBLK, 256>>>();
    k_scan3<<<NBLK, 256>>>();
    k_scatter_prep<<<(NE + TB - 1) / TB, TB>>>(ei, ea, x, sdf, nat);

    for (int l = 0; l < 6; l++) {
        const int inc = IN_C[l];
        const int K = 3 * inc;
        const int NC = (K + 31) / 32;
        const int Kpad = NC * 32;

        k_aggr<<<(NN + 63) / 64, 256>>>(inc, Kpad, win[l], bin[l]);
        if (l < 5) {
            k_permw_f16<<<(512 * Kpad + TB - 1) / TB, TB>>>(wout[l], inc, Kpad);
            dim3 grid(4, (NN + 127) / 128);
            k_gemm_mma<<<grid, 256, SMTOT>>>(NN, NC, bout[l], COFF[l]);
        } else {
            k_gemm_small<<<(NN + 7) / 8, 256>>>(inc, wout[l], bout[l], out);
        }
        if (l == 0) {
            k_setcol<<<(NN + TB - 1) / TB, TB>>>(512, nat);
        } else if (l == 2) {
            k_copyfy<<<(NN * 3 + TB - 1) / TB, TB>>>(fy);
            k_setcol<<<(NN + TB - 1) / TB, TB>>>(515, nat);
        } else if (l == 3) {
            k_setcol<<<(NN + TB - 1) / TB, TB>>>(512, nat);
        }
    }
}

// round 15
// speedup vs baseline: 1.1236x; 1.0911x over previous
#include <cuda_runtime.h>
#include <cuda_fp16.h>
#include <math.h>
#include <stdint.h>

#define NN 50000
#define NE 200000
#define XLD 516      // xc row stride (floats)
#define AP  1600     // fp16 A/B row stride (multiple of 64)
#define NBLK 196     // scan blocks (ceil(NN/256))
#define ESTG 1024    // edge window staged in smem per 64-node group

// ---------------- scratch ----------------
__device__ float g_xc[(size_t)NN * XLD];
__device__ __align__(16) __half g_ah[(size_t)NN * AP];
__device__ __align__(16) __half g_wh[(size_t)512 * AP];
__device__ int   g_cnt[NN];
__device__ int   g_bsum[NBLK];
__device__ int   g_rowptr[NN + 1];
__device__ int   g_cursor[NN];
__device__ int   g_src[NE];
__device__ __align__(16) float g_ea[(size_t)NE * 8];   // padded to 8 for LDG.128
__device__ int   g_is64;
__device__ int   g_arrive;

// ---------------- helpers ----------------
__device__ __forceinline__ uint32_t su32(const void* p) {
    uint32_t a;
    asm("{ .reg .u64 t; cvta.to.shared.u64 t, %1; cvt.u32.u64 %0, t; }" : "=r"(a) : "l"(p));
    return a;
}
__device__ __forceinline__ void ldm4(uint32_t* r, uint32_t addr) {
    asm volatile("ldmatrix.sync.aligned.m8n8.x4.shared.b16 {%0,%1,%2,%3}, [%4];"
                 : "=r"(r[0]), "=r"(r[1]), "=r"(r[2]), "=r"(r[3]) : "r"(addr));
}
__device__ __forceinline__ void mma16816(float* d, const uint32_t* a, const uint32_t* b) {
    asm volatile(
        "mma.sync.aligned.m16n8k16.row.col.f32.f16.f16.f32 "
        "{%0,%1,%2,%3}, {%4,%5,%6,%7}, {%8,%9}, {%0,%1,%2,%3};"
        : "+f"(d[0]), "+f"(d[1]), "+f"(d[2]), "+f"(d[3])
        : "r"(a[0]), "r"(a[1]), "r"(a[2]), "r"(a[3]), "r"(b[0]), "r"(b[1]));
}
__device__ __forceinline__ void cpa16(uint32_t dst, const void* src) {
    asm volatile("cp.async.cg.shared.global [%0], [%1], 16;" :: "r"(dst), "l"(src));
}
__device__ __forceinline__ void cp_commit() {
    asm volatile("cp.async.commit_group;" ::: "memory");
}
template <int N>
__device__ __forceinline__ void cp_wait() {
    asm volatile("cp.async.wait_group %0;" :: "n"(N) : "memory");
}
__device__ __forceinline__ float ftanh(float x) {
    float e = __expf(2.0f * x);
    return 1.0f - __fdividef(2.0f, e + 1.0f);
}

__device__ __forceinline__ int eload(const void* ei, int pos) {
    if (g_is64) return (int)((const long long*)ei)[pos];
    return ((const int*)ei)[pos];
}

// ---------------- (1) zero counters + detect edge_index dtype ----------------
__global__ void k_zero_detect(const int* ei32) {
    int i = blockIdx.x * blockDim.x + threadIdx.x;
    if (i < NN) g_cnt[i] = 0;
    if (i == 0) {
        g_arrive = 0;
        int z = 1;
        for (int k = 0; k < 64; k++)
            if (ei32[2 * k + 1] != 0) { z = 0; break; }
        g_is64 = z;
    }
}

// ---------------- (2) histogram of dst ----------------
__global__ void k_hist(const void* ei) {
    int e = blockIdx.x * blockDim.x + threadIdx.x;
    if (e < NE) atomicAdd(&g_cnt[eload(ei, NE + e)], 1);
}

// ---------------- (3) block sums + last-block scan of block sums ----------------
__global__ void k_scan12() {
    __shared__ int sm[256];
    __shared__ int lastFlag;
    int i = blockIdx.x * 256 + threadIdx.x;
    sm[threadIdx.x] = (i < NN) ? g_cnt[i] : 0;
    __syncthreads();
    for (int off = 128; off; off >>= 1) {
        if (threadIdx.x < off) sm[threadIdx.x] += sm[threadIdx.x + off];
        __syncthreads();
    }
    if (threadIdx.x == 0) {
        g_bsum[blockIdx.x] = sm[0];
        __threadfence();
        int t = atomicAdd(&g_arrive, 1);
        lastFlag = (t == gridDim.x - 1);
    }
    __syncthreads();
    if (lastFlag) {
        int t = threadIdx.x;
        int v = (t < NBLK) ? g_bsum[t] : 0;
        sm[t] = v;
        __syncthreads();
        for (int off = 1; off < 256; off <<= 1) {
            int u = (t >= off) ? sm[t - off] : 0;
            __syncthreads();
            sm[t] += u;
            __syncthreads();
        }
        if (t < NBLK) g_bsum[t] = sm[t] - v;
        if (t == NBLK - 1) g_rowptr[NN] = sm[t];
    }
}

// ---------------- (4) per-block exclusive scan -> rowptr, cursor ----------------
__global__ void k_scan3() {
    __shared__ int sm[256];
    int i = blockIdx.x * 256 + threadIdx.x;
    int v = (i < NN) ? g_cnt[i] : 0;
    sm[threadIdx.x] = v;
    __syncthreads();
    for (int off = 1; off < 256; off <<= 1) {
        int u = (threadIdx.x >= off) ? sm[threadIdx.x - off] : 0;
        __syncthreads();
        sm[threadIdx.x] += u;
        __syncthreads();
    }
    if (i < NN) {
        int ex = sm[threadIdx.x] - v + g_bsum[blockIdx.x];
        g_rowptr[i] = ex;
        g_cursor[i] = ex;
    }
}

// ---------------- (5) scatter edges to CSR + prep xc rows ----------------
__global__ void k_scatter_prep(const void* ei, const float* __restrict__ ea,
                               const float* __restrict__ x, const float* __restrict__ sdf,
                               const float* __restrict__ nat) {
    int idx = blockIdx.x * blockDim.x + threadIdx.x;
    if (idx < NE) {
        int e = idx;
        int d = eload(ei, NE + e);
        int s = eload(ei, e);
        int pos = atomicAdd(&g_cursor[d], 1);
        g_src[pos] = s;
        float4 v0 = make_float4(ea[e * 6 + 0], ea[e * 6 + 1], ea[e * 6 + 2], ea[e * 6 + 3]);
        float4 v1 = make_float4(ea[e * 6 + 4], ea[e * 6 + 5], 0.f, 0.f);
        *(float4*)(g_ea + (size_t)pos * 8)     = v0;
        *(float4*)(g_ea + (size_t)pos * 8 + 4) = v1;
    }
    if (idx < NN) {
        float* r = &g_xc[(size_t)idx * XLD];
#pragma unroll
        for (int c = 0; c < 5; c++) r[c] = x[idx * 5 + c];
        r[5] = sdf[idx];
        r[6] = nat[idx];
    }
}

// ---------------- xc concat fixups ----------------
__global__ void k_setcol(int col, const float* __restrict__ src) {
    int n = blockIdx.x * blockDim.x + threadIdx.x;
    if (n < NN) g_xc[(size_t)n * XLD + col] = src[n];
}
__global__ void k_copyfy(const float* __restrict__ fy) {
    int idx = blockIdx.x * blockDim.x + threadIdx.x;
    if (idx >= NN * 3) return;
    int n = idx / 3, c = idx - n * 3;
    g_xc[(size_t)n * XLD + c] = fy[idx];
}

// ---------------- weight prep: fp16, permuted k = h*in_c + i ----------------
__global__ void k_permw_f16(const float* __restrict__ wout, int in_c, int Kpad) {
    int K = 3 * in_c;
    int idx = blockIdx.x * blockDim.x + threadIdx.x;
    if (idx >= 512 * Kpad) return;
    int o = idx / Kpad, k = idx - o * Kpad;
    float v = 0.f;
    if (k < K) {
        int h = k / in_c, i = k - h * in_c;
        v = wout[(size_t)o * K + i * 3 + h];
    }
    g_wh[(size_t)o * AP + k] = __float2half_rn(v);
}

// ---------------- (6) fused scaling + gather + segment-sum -> fp16 ----------------
// R12 structure (group-level windows, scalar FMA, register weights) — proven best.
__global__ void __launch_bounds__(256, 2) k_aggr(int in_c, int kpad,
                                                 const float* __restrict__ win,
                                                 const float* __restrict__ bin) {
    __shared__ float s_ea[ESTG * 8];
    __shared__ int   s_src[ESTG];
    const int tid = threadIdx.x;
    const int i0 = tid, i1 = tid + 256, i2 = tid + 512;
    const bool v1 = (i1 < in_c), v2 = (i2 < in_c);

    float w0[18], w1[18], w2[18];
#pragma unroll
    for (int t = 0; t < 18; t++) {
        w0[t] = (i0 < in_c) ? win[i0 * 18 + t] : 0.f;
        w1[t] = v1 ? win[i1 * 18 + t] : 0.f;
        w2[t] = v2 ? win[i2 * 18 + t] : 0.f;
    }
    float b0[3], b1[3], b2[3];
#pragma unroll
    for (int h = 0; h < 3; h++) {
        b0[h] = (i0 < in_c) ? bin[i0 * 3 + h] : 0.f;
        b1[h] = v1 ? bin[i1 * 3 + h] : 0.f;
        b2[h] = v2 ? bin[i2 * 3 + h] : 0.f;
    }

    const int R = 3 * in_c, pad = kpad - R;
    const int n0 = blockIdx.x * 64;
    const int nend = (n0 + 64 < NN) ? n0 + 64 : NN;
    const int e0 = g_rowptr[n0], e1 = g_rowptr[nend];

    float a0[3] = {0.f, 0.f, 0.f}, a1[3] = {0.f, 0.f, 0.f}, a2[3] = {0.f, 0.f, 0.f};
    int n = n0;
    int ws = e0;
    while (true) {
        int wc = e1 - ws;
        if (wc > ESTG) wc = ESTG;
        if (wc < 0) wc = 0;
        __syncthreads();
        for (int t = tid; t < wc * 8; t += 256) s_ea[t] = g_ea[(size_t)ws * 8 + t];
        for (int t = tid; t < wc; t += 256) s_src[t] = g_src[ws + t];
        __syncthreads();
        const int wend = ws + wc;

        while (n < nend) {
            const int rs = g_rowptr[n], re = g_rowptr[n + 1];
            const int js = (rs > ws) ? rs : ws;
            const int je = (re < wend) ? re : wend;
            for (int j = js; j < je; j++) {
                const int lj = j - ws;
                const int s = s_src[lj];
                const float xv0 = __ldg(&g_xc[(size_t)s * XLD + i0]);
                const float xv1 = v1 ? __ldg(&g_xc[(size_t)s * XLD + i1]) : 0.f;
                const float xv2 = v2 ? __ldg(&g_xc[(size_t)s * XLD + i2]) : 0.f;
                const float4 ef0 = *(const float4*)&s_ea[lj * 8];
                const float2 ef1 = *(const float2*)&s_ea[lj * 8 + 4];
                const float ev[6] = {ef0.x, ef0.y, ef0.z, ef0.w, ef1.x, ef1.y};
                {
                    float s0 = b0[0], s1 = b0[1], s2 = b0[2];
#pragma unroll
                    for (int a = 0; a < 6; a++) {
                        float e = ev[a];
                        s0 = fmaf(e, w0[a], s0);
                        s1 = fmaf(e, w0[6 + a], s1);
                        s2 = fmaf(e, w0[12 + a], s2);
                    }
                    a0[0] = fmaf(fmaxf(s0, 0.f), xv0, a0[0]);
                    a0[1] = fmaf(fmaxf(s1, 0.f), xv0, a0[1]);
                    a0[2] = fmaf(fmaxf(s2, 0.f), xv0, a0[2]);
                }
                {
                    float s0 = b1[0], s1 = b1[1], s2 = b1[2];
#pragma unroll
                    for (int a = 0; a < 6; a++) {
                        float e = ev[a];
                        s0 = fmaf(e, w1[a], s0);
                        s1 = fmaf(e, w1[6 + a], s1);
                        s2 = fmaf(e, w1[12 + a], s2);
                    }
                    a1[0] = fmaf(fmaxf(s0, 0.f), xv1, a1[0]);
                    a1[1] = fmaf(fmaxf(s1, 0.f), xv1, a1[1]);
                    a1[2] = fmaf(fmaxf(s2, 0.f), xv1, a1[2]);
                }
                {
                    float s0 = b2[0], s1 = b2[1], s2 = b2[2];
#pragma unroll
                    for (int a = 0; a < 6; a++) {
                        float e = ev[a];
                        s0 = fmaf(e, w2[a], s0);
                        s1 = fmaf(e, w2[6 + a], s1);
                        s2 = fmaf(e, w2[12 + a], s2);
                    }
                    a2[0] = fmaf(fmaxf(s0, 0.f), xv2, a2[0]);
                    a2[1] = fmaf(fmaxf(s1, 0.f), xv2, a2[1]);
                    a2[2] = fmaf(fmaxf(s2, 0.f), xv2, a2[2]);
                }
            }
            if (re <= wend) {
                const size_t rb = (size_t)n * AP;
                if (i0 < in_c) {
                    g_ah[rb + i0]            = __float2half_rn(a0[0]);
                    g_ah[rb + in_c + i0]     = __float2half_rn(a0[1]);
                    g_ah[rb + 2 * in_c + i0] = __float2half_rn(a0[2]);
                }
                if (v1) {
                    g_ah[rb + i1]            = __float2half_rn(a1[0]);
                    g_ah[rb + in_c + i1]     = __float2half_rn(a1[1]);
                    g_ah[rb + 2 * in_c + i1] = __float2half_rn(a1[2]);
                }
                if (v2) {
                    g_ah[rb + i2]            = __float2half_rn(a2[0]);
                    g_ah[rb + in_c + i2]     = __float2half_rn(a2[1]);
                    g_ah[rb + 2 * in_c + i2] = __float2half_rn(a2[2]);
                }
                for (int p = tid; p < pad; p += 256)
                    g_ah[rb + R + p] = __float2half_rn(0.f);
#pragma unroll
                for (int q = 0; q < 3; q++) { a0[q] = 0.f; a1[q] = 0.f; a2[q] = 0.f; }
                n++;
            } else {
                break;   // node straddles window; carry acc to next window
            }
        }
        if (n >= nend) break;
        ws += ESTG;
    }
}

// ---------------- fp16 HMMA GEMM, 128x128 tile, K-chunk 64, cp.async 2-stage ----------------
#define SROW  144                 // 128B row + 16B pad (4-bank row offset, conflict-free)
#define SA    0
#define SB    (128 * SROW)        // 18432
#define STGSZ (2 * 128 * SROW)    // 36864
#define SMTOT (2 * STGSZ)         // 73728

__device__ __forceinline__ void gemm_issue(uint32_t st, int c, int tid,
                                           int m0, int n0, int M) {
#pragma unroll
    for (int it = 0; it < 4; it++) {
        int t = tid + it * 256;
        int row = t >> 3, c16 = t & 7;
        int rga = m0 + row; if (rga >= M) rga = M - 1;
        size_t ka = (size_t)c * 64 + c16 * 8;
        uint32_t d = st + row * SROW + c16 * 16;
        cpa16(d + SA, g_ah + (size_t)rga * AP + ka);
        cpa16(d + SB, g_wh + (size_t)(n0 + row) * AP + ka);
    }
    cp_commit();
}

__global__ void __launch_bounds__(256, 2) k_gemm_mma(int M, int NC,
                                                     const float* __restrict__ bias,
                                                     int coloff) {
    extern __shared__ __align__(16) char dsm[];
    const int tid = threadIdx.x;
    const int wid = tid >> 5;
    const int lane = tid & 31;
    const int m0 = blockIdx.y * 128;
    const int n0 = blockIdx.x * 128;
    const uint32_t sb = su32(dsm);

    const int wm = (wid >> 2) * 64;
    const int wn = (wid & 3) * 32;

    float acc[4][4][4];
#pragma unroll
    for (int mt = 0; mt < 4; mt++)
#pragma unroll
        for (int nt = 0; nt < 4; nt++)
#pragma unroll
            for (int q = 0; q < 4; q++) acc[mt][nt][q] = 0.f;

    gemm_issue(sb, 0, tid, m0, n0, M);

    for (int c = 0; c < NC; c++) {
        const int b = c & 1;
        if (c + 1 < NC) {
            gemm_issue(sb + ((c + 1) & 1) * STGSZ, c + 1, tid, m0, n0, M);
            cp_wait<1>();
        } else {
            cp_wait<0>();
        }
        __syncthreads();

        const uint32_t st = sb + b * STGSZ;
#pragma unroll
        for (int s = 0; s < 4; s++) {
            uint32_t ah[4][4];
#pragma unroll
            for (int mt = 0; mt < 4; mt++) {
                uint32_t row = wm + mt * 16 + (lane & 15);
                uint32_t ad = st + SA + row * SROW + s * 32 + (lane >> 4) * 16;
                ldm4(ah[mt], ad);
            }
            uint32_t bh[4][2];
#pragma unroll
            for (int p = 0; p < 2; p++) {
                uint32_t row = wn + p * 16 + (lane & 7) + (lane >> 4) * 8;
                uint32_t bd = st + SB + row * SROW + s * 32 + ((lane >> 3) & 1) * 16;
                uint32_t r[4];
                ldm4(r, bd);
                bh[2 * p][0] = r[0]; bh[2 * p][1] = r[1];
                bh[2 * p + 1][0] = r[2]; bh[2 * p + 1][1] = r[3];
            }
#pragma unroll
            for (int mt = 0; mt < 4; mt++)
#pragma unroll
                for (int nt = 0; nt < 4; nt++)
                    mma16816(acc[mt][nt], ah[mt], bh[nt]);
        }
        __syncthreads();
    }

#pragma unroll
    for (int mt = 0; mt < 4; mt++) {
        int gm0 = m0 + wm + mt * 16 + (lane >> 2);
        int gm1 = gm0 + 8;
#pragma unroll
        for (int nt = 0; nt < 4; nt++) {
            int cn = n0 + wn + nt * 8 + (lane & 3) * 2;
            float b0 = bias[cn], b1 = bias[cn + 1];
            if (gm0 < M) {
                float* p = &g_xc[(size_t)gm0 * XLD + coloff + cn];
                p[0] = fmaxf(ftanh(acc[mt][nt][0] + b0), 0.f);
                p[1] = fmaxf(ftanh(acc[mt][nt][1] + b1), 0.f);
            }
            if (gm1 < M) {
                float* p = &g_xc[(size_t)gm1 * XLD + coloff + cn];
                p[0] = fmaxf(ftanh(acc[mt][nt][2] + b0), 0.f);
                p[1] = fmaxf(ftanh(acc[mt][nt][3] + b1), 0.f);
            }
        }
    }
}

// ---------------- last layer (out_c = 3): warp per node, fp32, tanh only ----------------
__global__ void __launch_bounds__(256) k_gemm_small(int in_c, const float* __restrict__ wout,
                                                    const float* __restrict__ bias,
                                                    float* __restrict__ out) {
    int node = blockIdx.x * 8 + (threadIdx.x >> 5);
    int lane = threadIdx.x & 31;
    if (node >= NN) return;
    const int K = 3 * in_c;
    const __half* hi = g_ah + (size_t)node * AP;
    float c0 = 0.f, c1 = 0.f, c2 = 0.f;
    for (int h = 0; h < 3; h++) {
        for (int i = lane; i < in_c; i += 32) {
            int k = h * in_c + i;
            float a = __half2float(hi[k]);
            int wi = i * 3 + h;
            c0 = fmaf(a, wout[0 * (size_t)K + wi], c0);
            c1 = fmaf(a, wout[1 * (size_t)K + wi], c1);
            c2 = fmaf(a, wout[2 * (size_t)K + wi], c2);
        }
    }
#pragma unroll
    for (int o = 16; o; o >>= 1) {
        c0 += __shfl_down_sync(0xffffffffu, c0, o);
        c1 += __shfl_down_sync(0xffffffffu, c1, o);
        c2 += __shfl_down_sync(0xffffffffu, c2, o);
    }
    if (lane == 0) {
        out[(size_t)node * 3 + 0] = tanhf(c0 + bias[0]);
        out[(size_t)node * 3 + 1] = tanhf(c1 + bias[1]);
        out[(size_t)node * 3 + 2] = tanhf(c2 + bias[2]);
    }
}

// ---------------- launch ----------------
extern "C" void kernel_launch(void* const* d_in, const int* in_sizes, int n_in,
                              void* d_out, int out_size) {
    (void)in_sizes; (void)n_in; (void)out_size;
    const float* x   = (const float*)d_in[0];
    const float* sdf = (const float*)d_in[1];
    const float* nat = (const float*)d_in[2];
    const float* ea  = (const float*)d_in[3];
    const float* fy  = (const float*)d_in[4];
    const void*  ei  = d_in[5];
    const float* win[6];  const float* bin[6];
    const float* wout[6]; const float* bout[6];
    for (int l = 0; l < 6; l++) {
        win[l]  = (const float*)d_in[6 + 4 * l];
        bin[l]  = (const float*)d_in[7 + 4 * l];
        wout[l] = (const float*)d_in[8 + 4 * l];
        bout[l] = (const float*)d_in[9 + 4 * l];
    }
    float* out = (float*)d_out;

    static const int IN_C[6] = {7, 513, 513, 516, 513, 513};
    static const int COFF[6] = {0, 0, 3, 0, 0, 0};

    cudaFuncSetAttribute(k_gemm_mma, cudaFuncAttributeMaxDynamicSharedMemorySize, SMTOT);

    const int TB = 256;
    k_zero_detect<<<(NN + TB - 1) / TB, TB>>>((const int*)ei);
    k_hist<<<(NE + TB - 1) / TB, TB>>>(ei);
    k_scan12<<<NBLK, 256>>>();
    k_scan3<<<NBLK, 256>>>();
    k_scatter_prep<<<(NE + TB - 1) / TB, TB>>>(ei, ea, x, sdf, nat);

    for (int l = 0; l < 6; l++) {
        const int inc = IN_C[l];
        const int K = 3 * inc;
        const int NC = (K + 63) / 64;
        const int Kpad = NC * 64;

        k_aggr<<<(NN + 63) / 64, 256>>>(inc, Kpad, win[l], bin[l]);
        if (l < 5) {
            k_permw_f16<<<(512 * Kpad + TB - 1) / TB, TB>>>(wout[l], inc, Kpad);
            dim3 grid(4, (NN + 127) / 128);
            k_gemm_mma<<<grid, 256, SMTOT>>>(NN, NC, bout[l], COFF[l]);
        } else {
            k_gemm_small<<<(NN + 7) / 8, 256>>>(inc, wout[l], bout[l], out);
        }
        if (l == 0) {
            k_setcol<<<(NN + TB - 1) / TB, TB>>>(512, nat);
        } else if (l == 2) {
            k_copyfy<<<(NN * 3 + TB - 1) / TB, TB>>>(fy);
            k_setcol<<<(NN + TB - 1) / TB, TB>>>(515, nat);
        } else if (l == 3) {
            k_setcol<<<(NN + TB - 1) / TB, TB>>>(512, nat);
        }
    }
}

// round 16
// speedup vs baseline: 1.1289x; 1.0047x over previous
#include <cuda_runtime.h>
#include <cuda_fp16.h>
#include <math.h>
#include <stdint.h>

#define NN 50000
#define NE 200000
#define XLD 516      // xc row stride (floats)
#define AP  1600     // fp16 A/B row stride (multiple of 64)
#define NBLK 196     // scan blocks (ceil(NN/256))
#define ESTG 1024    // edge window staged in smem per 64-node group

// ---------------- scratch ----------------
__device__ float g_xc[(size_t)NN * XLD];
__device__ __align__(16) __half g_ah[(size_t)NN * AP];
__device__ __align__(16) __half g_wh[(size_t)512 * AP];
__device__ int   g_cnt[NN];
__device__ int   g_bsum[NBLK];
__device__ int   g_rowptr[NN + 1];
__device__ int   g_cursor[NN];
__device__ int   g_src[NE];
__device__ __align__(16) float g_ea[(size_t)NE * 8];   // padded to 8 for LDG.128
__device__ int   g_is64;
__device__ int   g_arrive;

// ---------------- helpers ----------------
__device__ __forceinline__ uint32_t su32(const void* p) {
    uint32_t a;
    asm("{ .reg .u64 t; cvta.to.shared.u64 t, %1; cvt.u32.u64 %0, t; }" : "=r"(a) : "l"(p));
    return a;
}
__device__ __forceinline__ void ldm4(uint32_t* r, uint32_t addr) {
    asm volatile("ldmatrix.sync.aligned.m8n8.x4.shared.b16 {%0,%1,%2,%3}, [%4];"
                 : "=r"(r[0]), "=r"(r[1]), "=r"(r[2]), "=r"(r[3]) : "r"(addr));
}
__device__ __forceinline__ void mma16816(float* d, const uint32_t* a, const uint32_t* b) {
    asm volatile(
        "mma.sync.aligned.m16n8k16.row.col.f32.f16.f16.f32 "
        "{%0,%1,%2,%3}, {%4,%5,%6,%7}, {%8,%9}, {%0,%1,%2,%3};"
        : "+f"(d[0]), "+f"(d[1]), "+f"(d[2]), "+f"(d[3])
        : "r"(a[0]), "r"(a[1]), "r"(a[2]), "r"(a[3]), "r"(b[0]), "r"(b[1]));
}
__device__ __forceinline__ void cpa16(uint32_t dst, const void* src) {
    asm volatile("cp.async.cg.shared.global [%0], [%1], 16;" :: "r"(dst), "l"(src));
}
__device__ __forceinline__ void cp_commit() {
    asm volatile("cp.async.commit_group;" ::: "memory");
}
template <int N>
__device__ __forceinline__ void cp_wait() {
    asm volatile("cp.async.wait_group %0;" :: "n"(N) : "memory");
}
__device__ __forceinline__ float ftanh(float x) {
    float e = __expf(2.0f * x);
    return 1.0f - __fdividef(2.0f, e + 1.0f);
}

__device__ __forceinline__ int eload(const void* ei, int pos) {
    if (g_is64) return (int)((const long long*)ei)[pos];
    return ((const int*)ei)[pos];
}

// ---------------- (1) zero counters + detect edge_index dtype ----------------
__global__ void k_zero_detect(const int* ei32) {
    int i = blockIdx.x * blockDim.x + threadIdx.x;
    if (i < NN) g_cnt[i] = 0;
    if (i == 0) {
        g_arrive = 0;
        int z = 1;
        for (int k = 0; k < 64; k++)
            if (ei32[2 * k + 1] != 0) { z = 0; break; }
        g_is64 = z;
    }
}

// ---------------- (2) histogram of dst ----------------
__global__ void k_hist(const void* ei) {
    int e = blockIdx.x * blockDim.x + threadIdx.x;
    if (e < NE) atomicAdd(&g_cnt[eload(ei, NE + e)], 1);
}

// ---------------- (3) block sums + last-block scan of block sums ----------------
__global__ void k_scan12() {
    __shared__ int sm[256];
    __shared__ int lastFlag;
    int i = blockIdx.x * 256 + threadIdx.x;
    sm[threadIdx.x] = (i < NN) ? g_cnt[i] : 0;
    __syncthreads();
    for (int off = 128; off; off >>= 1) {
        if (threadIdx.x < off) sm[threadIdx.x] += sm[threadIdx.x + off];
        __syncthreads();
    }
    if (threadIdx.x == 0) {
        g_bsum[blockIdx.x] = sm[0];
        __threadfence();
        int t = atomicAdd(&g_arrive, 1);
        lastFlag = (t == gridDim.x - 1);
    }
    __syncthreads();
    if (lastFlag) {
        int t = threadIdx.x;
        int v = (t < NBLK) ? g_bsum[t] : 0;
        sm[t] = v;
        __syncthreads();
        for (int off = 1; off < 256; off <<= 1) {
            int u = (t >= off) ? sm[t - off] : 0;
            __syncthreads();
            sm[t] += u;
            __syncthreads();
        }
        if (t < NBLK) g_bsum[t] = sm[t] - v;
        if (t == NBLK - 1) g_rowptr[NN] = sm[t];
    }
}

// ---------------- (4) per-block exclusive scan -> rowptr, cursor ----------------
__global__ void k_scan3() {
    __shared__ int sm[256];
    int i = blockIdx.x * 256 + threadIdx.x;
    int v = (i < NN) ? g_cnt[i] : 0;
    sm[threadIdx.x] = v;
    __syncthreads();
    for (int off = 1; off < 256; off <<= 1) {
        int u = (threadIdx.x >= off) ? sm[threadIdx.x - off] : 0;
        __syncthreads();
        sm[threadIdx.x] += u;
        __syncthreads();
    }
    if (i < NN) {
        int ex = sm[threadIdx.x] - v + g_bsum[blockIdx.x];
        g_rowptr[i] = ex;
        g_cursor[i] = ex;
    }
}

// ---------------- (5) scatter edges to CSR + prep xc rows ----------------
__global__ void k_scatter_prep(const void* ei, const float* __restrict__ ea,
                               const float* __restrict__ x, const float* __restrict__ sdf,
                               const float* __restrict__ nat) {
    int idx = blockIdx.x * blockDim.x + threadIdx.x;
    if (idx < NE) {
        int e = idx;
        int d = eload(ei, NE + e);
        int s = eload(ei, e);
        int pos = atomicAdd(&g_cursor[d], 1);
        g_src[pos] = s;
        float4 v0 = make_float4(ea[e * 6 + 0], ea[e * 6 + 1], ea[e * 6 + 2], ea[e * 6 + 3]);
        float4 v1 = make_float4(ea[e * 6 + 4], ea[e * 6 + 5], 0.f, 0.f);
        *(float4*)(g_ea + (size_t)pos * 8)     = v0;
        *(float4*)(g_ea + (size_t)pos * 8 + 4) = v1;
    }
    if (idx < NN) {
        float* r = &g_xc[(size_t)idx * XLD];
#pragma unroll
        for (int c = 0; c < 5; c++) r[c] = x[idx * 5 + c];
        r[5] = sdf[idx];
        r[6] = nat[idx];
    }
}

// ---------------- xc concat fixups ----------------
__global__ void k_setcol(int col, const float* __restrict__ src) {
    int n = blockIdx.x * blockDim.x + threadIdx.x;
    if (n < NN) g_xc[(size_t)n * XLD + col] = src[n];
}
__global__ void k_copyfy(const float* __restrict__ fy) {
    int idx = blockIdx.x * blockDim.x + threadIdx.x;
    if (idx >= NN * 3) return;
    int n = idx / 3, c = idx - n * 3;
    g_xc[(size_t)n * XLD + c] = fy[idx];
}

// ---------------- weight prep: fp16, permuted k = h*in_c + i ----------------
__global__ void k_permw_f16(const float* __restrict__ wout, int in_c, int Kpad) {
    int K = 3 * in_c;
    int idx = blockIdx.x * blockDim.x + threadIdx.x;
    if (idx >= 512 * Kpad) return;
    int o = idx / Kpad, k = idx - o * Kpad;
    float v = 0.f;
    if (k < K) {
        int h = k / in_c, i = k - h * in_c;
        v = wout[(size_t)o * K + i * 3 + h];
    }
    g_wh[(size_t)o * AP + k] = __float2half_rn(v);
}

// ---------------- (6) fused scaling + gather + segment-sum -> fp16 ----------------
// R12 structure; third channel set (tid+512, valid only for tid<4) now branch-guarded
// so 7 of 8 warps skip its FMA block entirely.
__global__ void __launch_bounds__(256, 2) k_aggr(int in_c, int kpad,
                                                 const float* __restrict__ win,
                                                 const float* __restrict__ bin) {
    __shared__ float s_ea[ESTG * 8];
    __shared__ int   s_src[ESTG];
    const int tid = threadIdx.x;
    const int i0 = tid, i1 = tid + 256, i2 = tid + 512;
    const bool v1 = (i1 < in_c), v2 = (i2 < in_c);

    float w0[18], w1[18], w2[18];
#pragma unroll
    for (int t = 0; t < 18; t++) {
        w0[t] = (i0 < in_c) ? win[i0 * 18 + t] : 0.f;
        w1[t] = v1 ? win[i1 * 18 + t] : 0.f;
        w2[t] = v2 ? win[i2 * 18 + t] : 0.f;
    }
    float b0[3], b1[3], b2[3];
#pragma unroll
    for (int h = 0; h < 3; h++) {
        b0[h] = (i0 < in_c) ? bin[i0 * 3 + h] : 0.f;
        b1[h] = v1 ? bin[i1 * 3 + h] : 0.f;
        b2[h] = v2 ? bin[i2 * 3 + h] : 0.f;
    }

    const int R = 3 * in_c, pad = kpad - R;
    const int n0 = blockIdx.x * 64;
    const int nend = (n0 + 64 < NN) ? n0 + 64 : NN;
    const int e0 = g_rowptr[n0], e1 = g_rowptr[nend];

    float a0[3] = {0.f, 0.f, 0.f}, a1[3] = {0.f, 0.f, 0.f}, a2[3] = {0.f, 0.f, 0.f};
    int n = n0;
    int ws = e0;
    while (true) {
        int wc = e1 - ws;
        if (wc > ESTG) wc = ESTG;
        if (wc < 0) wc = 0;
        __syncthreads();
        for (int t = tid; t < wc * 8; t += 256) s_ea[t] = g_ea[(size_t)ws * 8 + t];
        for (int t = tid; t < wc; t += 256) s_src[t] = g_src[ws + t];
        __syncthreads();
        const int wend = ws + wc;

        while (n < nend) {
            const int rs = g_rowptr[n], re = g_rowptr[n + 1];
            const int js = (rs > ws) ? rs : ws;
            const int je = (re < wend) ? re : wend;
            for (int j = js; j < je; j++) {
                const int lj = j - ws;
                const int s = s_src[lj];
                const float xv0 = __ldg(&g_xc[(size_t)s * XLD + i0]);
                const float xv1 = v1 ? __ldg(&g_xc[(size_t)s * XLD + i1]) : 0.f;
                const float4 ef0 = *(const float4*)&s_ea[lj * 8];
                const float2 ef1 = *(const float2*)&s_ea[lj * 8 + 4];
                const float ev[6] = {ef0.x, ef0.y, ef0.z, ef0.w, ef1.x, ef1.y};
                {
                    float s0 = b0[0], s1 = b0[1], s2 = b0[2];
#pragma unroll
                    for (int a = 0; a < 6; a++) {
                        float e = ev[a];
                        s0 = fmaf(e, w0[a], s0);
                        s1 = fmaf(e, w0[6 + a], s1);
                        s2 = fmaf(e, w0[12 + a], s2);
                    }
                    a0[0] = fmaf(fmaxf(s0, 0.f), xv0, a0[0]);
                    a0[1] = fmaf(fmaxf(s1, 0.f), xv0, a0[1]);
                    a0[2] = fmaf(fmaxf(s2, 0.f), xv0, a0[2]);
                }
                {
                    float s0 = b1[0], s1 = b1[1], s2 = b1[2];
#pragma unroll
                    for (int a = 0; a < 6; a++) {
                        float e = ev[a];
                        s0 = fmaf(e, w1[a], s0);
                        s1 = fmaf(e, w1[6 + a], s1);
                        s2 = fmaf(e, w1[12 + a], s2);
                    }
                    a1[0] = fmaf(fmaxf(s0, 0.f), xv1, a1[0]);
                    a1[1] = fmaf(fmaxf(s1, 0.f), xv1, a1[1]);
                    a1[2] = fmaf(fmaxf(s2, 0.f), xv1, a1[2]);
                }
                if (v2) {   // only warp 0 (lanes 0..3) ever enters; others skip entirely
                    const float xv2 = __ldg(&g_xc[(size_t)s * XLD + i2]);
                    float s0 = b2[0], s1 = b2[1], s2 = b2[2];
#pragma unroll
                    for (int a = 0; a < 6; a++) {
                        float e = ev[a];
                        s0 = fmaf(e, w2[a], s0);
                        s1 = fmaf(e, w2[6 + a], s1);
                        s2 = fmaf(e, w2[12 + a], s2);
                    }
                    a2[0] = fmaf(fmaxf(s0, 0.f), xv2, a2[0]);
                    a2[1] = fmaf(fmaxf(s1, 0.f), xv2, a2[1]);
                    a2[2] = fmaf(fmaxf(s2, 0.f), xv2, a2[2]);
                }
            }
            if (re <= wend) {
                const size_t rb = (size_t)n * AP;
                if (i0 < in_c) {
                    g_ah[rb + i0]            = __float2half_rn(a0[0]);
                    g_ah[rb + in_c + i0]     = __float2half_rn(a0[1]);
                    g_ah[rb + 2 * in_c + i0] = __float2half_rn(a0[2]);
                }
                if (v1) {
                    g_ah[rb + i1]            = __float2half_rn(a1[0]);
                    g_ah[rb + in_c + i1]     = __float2half_rn(a1[1]);
                    g_ah[rb + 2 * in_c + i1] = __float2half_rn(a1[2]);
                }
                if (v2) {
                    g_ah[rb + i2]            = __float2half_rn(a2[0]);
                    g_ah[rb + in_c + i2]     = __float2half_rn(a2[1]);
                    g_ah[rb + 2 * in_c + i2] = __float2half_rn(a2[2]);
                }
                for (int p = tid; p < pad; p += 256)
                    g_ah[rb + R + p] = __float2half_rn(0.f);
#pragma unroll
                for (int q = 0; q < 3; q++) { a0[q] = 0.f; a1[q] = 0.f; a2[q] = 0.f; }
                n++;
            } else {
                break;   // node straddles window; carry acc to next window
            }
        }
        if (n >= nend) break;
        ws += ESTG;
    }
}

// ---------------- fp16 HMMA GEMM, 128x128 tile, K-chunk 64, cp.async 2-stage ----------------
#define SROW  144                 // 128B row + 16B pad (4-bank row offset, conflict-free)
#define SA    0
#define SB    (128 * SROW)        // 18432
#define STGSZ (2 * 128 * SROW)    // 36864
#define SMTOT (2 * STGSZ)         // 73728

__device__ __forceinline__ void gemm_issue(uint32_t st, int c, int tid,
                                           int m0, int n0, int M) {
#pragma unroll
    for (int it = 0; it < 4; it++) {
        int t = tid + it * 256;
        int row = t >> 3, c16 = t & 7;
        int rga = m0 + row; if (rga >= M) rga = M - 1;
        size_t ka = (size_t)c * 64 + c16 * 8;
        uint32_t d = st + row * SROW + c16 * 16;
        cpa16(d + SA, g_ah + (size_t)rga * AP + ka);
        cpa16(d + SB, g_wh + (size_t)(n0 + row) * AP + ka);
    }
    cp_commit();
}

__global__ void __launch_bounds__(256, 2) k_gemm_mma(int M, int NC,
                                                     const float* __restrict__ bias,
                                                     int coloff) {
    extern __shared__ __align__(16) char dsm[];
    const int tid = threadIdx.x;
    const int wid = tid >> 5;
    const int lane = tid & 31;
    const int m0 = blockIdx.y * 128;
    const int n0 = blockIdx.x * 128;
    const uint32_t sb = su32(dsm);

    const int wm = (wid >> 2) * 64;
    const int wn = (wid & 3) * 32;

    float acc[4][4][4];
#pragma unroll
    for (int mt = 0; mt < 4; mt++)
#pragma unroll
        for (int nt = 0; nt < 4; nt++)
#pragma unroll
            for (int q = 0; q < 4; q++) acc[mt][nt][q] = 0.f;

    gemm_issue(sb, 0, tid, m0, n0, M);

    for (int c = 0; c < NC; c++) {
        const int b = c & 1;
        if (c + 1 < NC) {
            gemm_issue(sb + ((c + 1) & 1) * STGSZ, c + 1, tid, m0, n0, M);
            cp_wait<1>();
        } else {
            cp_wait<0>();
        }
        __syncthreads();

        const uint32_t st = sb + b * STGSZ;
#pragma unroll
        for (int s = 0; s < 4; s++) {
            uint32_t ah[4][4];
#pragma unroll
            for (int mt = 0; mt < 4; mt++) {
                uint32_t row = wm + mt * 16 + (lane & 15);
                uint32_t ad = st + SA + row * SROW + s * 32 + (lane >> 4) * 16;
                ldm4(ah[mt], ad);
            }
            uint32_t bh[4][2];
#pragma unroll
            for (int p = 0; p < 2; p++) {
                uint32_t row = wn + p * 16 + (lane & 7) + (lane >> 4) * 8;
                uint32_t bd = st + SB + row * SROW + s * 32 + ((lane >> 3) & 1) * 16;
                uint32_t r[4];
                ldm4(r, bd);
                bh[2 * p][0] = r[0]; bh[2 * p][1] = r[1];
                bh[2 * p + 1][0] = r[2]; bh[2 * p + 1][1] = r[3];
            }
#pragma unroll
            for (int mt = 0; mt < 4; mt++)
#pragma unroll
                for (int nt = 0; nt < 4; nt++)
                    mma16816(acc[mt][nt], ah[mt], bh[nt]);
        }
        __syncthreads();
    }

#pragma unroll
    for (int mt = 0; mt < 4; mt++) {
        int gm0 = m0 + wm + mt * 16 + (lane >> 2);
        int gm1 = gm0 + 8;
#pragma unroll
        for (int nt = 0; nt < 4; nt++) {
            int cn = n0 + wn + nt * 8 + (lane & 3) * 2;
            float b0 = bias[cn], b1 = bias[cn + 1];
            if (gm0 < M) {
                float* p = &g_xc[(size_t)gm0 * XLD + coloff + cn];
                p[0] = fmaxf(ftanh(acc[mt][nt][0] + b0), 0.f);
                p[1] = fmaxf(ftanh(acc[mt][nt][1] + b1), 0.f);
            }
            if (gm1 < M) {
                float* p = &g_xc[(size_t)gm1 * XLD + coloff + cn];
                p[0] = fmaxf(ftanh(acc[mt][nt][2] + b0), 0.f);
                p[1] = fmaxf(ftanh(acc[mt][nt][3] + b1), 0.f);
            }
        }
    }
}

// ---------------- last layer (out_c = 3): warp per node, fp32, tanh only ----------------
__global__ void __launch_bounds__(256) k_gemm_small(int in_c, const float* __restrict__ wout,
                                                    const float* __restrict__ bias,
                                                    float* __restrict__ out) {
    int node = blockIdx.x * 8 + (threadIdx.x >> 5);
    int lane = threadIdx.x & 31;
    if (node >= NN) return;
    const int K = 3 * in_c;
    const __half* hi = g_ah + (size_t)node * AP;
    float c0 = 0.f, c1 = 0.f, c2 = 0.f;
    for (int h = 0; h < 3; h++) {
        for (int i = lane; i < in_c; i += 32) {
            int k = h * in_c + i;
            float a = __half2float(hi[k]);
            int wi = i * 3 + h;
            c0 = fmaf(a, wout[0 * (size_t)K + wi], c0);
            c1 = fmaf(a, wout[1 * (size_t)K + wi], c1);
            c2 = fmaf(a, wout[2 * (size_t)K + wi], c2);
        }
    }
#pragma unroll
    for (int o = 16; o; o >>= 1) {
        c0 += __shfl_down_sync(0xffffffffu, c0, o);
        c1 += __shfl_down_sync(0xffffffffu, c1, o);
        c2 += __shfl_down_sync(0xffffffffu, c2, o);
    }
    if (lane == 0) {
        out[(size_t)node * 3 + 0] = tanhf(c0 + bias[0]);
        out[(size_t)node * 3 + 1] = tanhf(c1 + bias[1]);
        out[(size_t)node * 3 + 2] = tanhf(c2 + bias[2]);
    }
}

// ---------------- launch ----------------
extern "C" void kernel_launch(void* const* d_in, const int* in_sizes, int n_in,
                              void* d_out, int out_size) {
    (void)in_sizes; (void)n_in; (void)out_size;
    const float* x   = (const float*)d_in[0];
    const float* sdf = (const float*)d_in[1];
    const float* nat = (const float*)d_in[2];
    const float* ea  = (const float*)d_in[3];
    const float* fy  = (const float*)d_in[4];
    const void*  ei  = d_in[5];
    const float* win[6];  const float* bin[6];
    const float* wout[6]; const float* bout[6];
    for (int l = 0; l < 6; l++) {
        win[l]  = (const float*)d_in[6 + 4 * l];
        bin[l]  = (const float*)d_in[7 + 4 * l];
        wout[l] = (const float*)d_in[8 + 4 * l];
        bout[l] = (const float*)d_in[9 + 4 * l];
    }
    float* out = (float*)d_out;

    static const int IN_C[6] = {7, 513, 513, 516, 513, 513};
    static const int COFF[6] = {0, 0, 3, 0, 0, 0};

    cudaFuncSetAttribute(k_gemm_mma, cudaFuncAttributeMaxDynamicSharedMemorySize, SMTOT);

    const int TB = 256;
    k_zero_detect<<<(NN + TB - 1) / TB, TB>>>((const int*)ei);
    k_hist<<<(NE + TB - 1) / TB, TB>>>(ei);
    k_scan12<<<NBLK, 256>>>();
    k_scan3<<<NBLK, 256>>>();
    k_scatter_prep<<<(NE + TB - 1) / TB, TB>>>(ei, ea, x, sdf, nat);

    for (int l = 0; l < 6; l++) {
        const int inc = IN_C[l];
        const int K = 3 * inc;
        const int NC = (K + 63) / 64;
        const int Kpad = NC * 64;

        k_aggr<<<(NN + 63) / 64, 256>>>(inc, Kpad, win[l], bin[l]);
        if (l < 5) {
            k_permw_f16<<<(512 * Kpad + TB - 1) / TB, TB>>>(wout[l], inc, Kpad);
            dim3 grid(4, (NN + 127) / 128);
            k_gemm_mma<<<grid, 256, SMTOT>>>(NN, NC, bout[l], COFF[l]);
        } else {
            k_gemm_small<<<(NN + 7) / 8, 256>>>(inc, wout[l], bout[l], out);
        }
        if (l == 0) {
            k_setcol<<<(NN + TB - 1) / TB, TB>>>(512, nat);
        } else if (l == 2) {
            k_copyfy<<<(NN * 3 + TB - 1) / TB, TB>>>(fy);
            k_setcol<<<(NN + TB - 1) / TB, TB>>>(515, nat);
        } else if (l == 3) {
            k_setcol<<<(NN + TB - 1) / TB, TB>>>(512, nat);
        }
    }
}

// round 17
// speedup vs baseline: 1.2044x; 1.0668x over previous
#include <cuda_runtime.h>
#include <cuda_fp16.h>
#include <math.h>
#include <stdint.h>

#define NN 50000
#define NE 200000
#define XLD 516      // xc row stride (floats)
#define AP  1600     // fp16 A/B row stride (multiple of 64)
#define NBLK 196     // scan blocks (ceil(NN/256))
#define ESTG 1024    // edge window staged in smem per 64-node group

// ---------------- scratch ----------------
__device__ float g_xc[(size_t)NN * XLD];
__device__ __align__(16) __half g_ah[(size_t)NN * AP];
__device__ __align__(16) __half g_wh[(size_t)512 * AP];
__device__ int   g_cnt[NN];
__device__ int   g_bsum[NBLK];
__device__ int   g_rowptr[NN + 1];
__device__ int   g_cursor[NN];
__device__ int   g_src[NE];
__device__ __align__(16) float g_ea[(size_t)NE * 8];   // padded to 8 for LDG.128
__device__ int   g_is64;
__device__ int   g_arrive;

// ---------------- helpers ----------------
__device__ __forceinline__ uint32_t su32(const void* p) {
    uint32_t a;
    asm("{ .reg .u64 t; cvta.to.shared.u64 t, %1; cvt.u32.u64 %0, t; }" : "=r"(a) : "l"(p));
    return a;
}
__device__ __forceinline__ void ldm4(uint32_t* r, uint32_t addr) {
    asm volatile("ldmatrix.sync.aligned.m8n8.x4.shared.b16 {%0,%1,%2,%3}, [%4];"
                 : "=r"(r[0]), "=r"(r[1]), "=r"(r[2]), "=r"(r[3]) : "r"(addr));
}
__device__ __forceinline__ void mma16816(float* d, const uint32_t* a, const uint32_t* b) {
    asm volatile(
        "mma.sync.aligned.m16n8k16.row.col.f32.f16.f16.f32 "
        "{%0,%1,%2,%3}, {%4,%5,%6,%7}, {%8,%9}, {%0,%1,%2,%3};"
        : "+f"(d[0]), "+f"(d[1]), "+f"(d[2]), "+f"(d[3])
        : "r"(a[0]), "r"(a[1]), "r"(a[2]), "r"(a[3]), "r"(b[0]), "r"(b[1]));
}
__device__ __forceinline__ void cpa16(uint32_t dst, const void* src) {
    asm volatile("cp.async.cg.shared.global [%0], [%1], 16;" :: "r"(dst), "l"(src));
}
__device__ __forceinline__ void cp_commit() {
    asm volatile("cp.async.commit_group;" ::: "memory");
}
template <int N>
__device__ __forceinline__ void cp_wait() {
    asm volatile("cp.async.wait_group %0;" :: "n"(N) : "memory");
}
__device__ __forceinline__ float ftanh(float x) {
    float e = __expf(2.0f * x);
    return 1.0f - __fdividef(2.0f, e + 1.0f);
}

__device__ __forceinline__ int eload(const void* ei, int pos) {
    if (g_is64) return (int)((const long long*)ei)[pos];
    return ((const int*)ei)[pos];
}

// ---------------- (1) zero counters + detect edge_index dtype ----------------
__global__ void k_zero_detect(const int* ei32) {
    int i = blockIdx.x * blockDim.x + threadIdx.x;
    if (i < NN) g_cnt[i] = 0;
    if (i == 0) {
        g_arrive = 0;
        int z = 1;
        for (int k = 0; k < 64; k++)
            if (ei32[2 * k + 1] != 0) { z = 0; break; }
        g_is64 = z;
    }
}

// ---------------- (2) histogram of dst ----------------
__global__ void k_hist(const void* ei) {
    int e = blockIdx.x * blockDim.x + threadIdx.x;
    if (e < NE) atomicAdd(&g_cnt[eload(ei, NE + e)], 1);
}

// ---------------- (3) block sums + last-block scan of block sums ----------------
__global__ void k_scan12() {
    __shared__ int sm[256];
    __shared__ int lastFlag;
    int i = blockIdx.x * 256 + threadIdx.x;
    sm[threadIdx.x] = (i < NN) ? g_cnt[i] : 0;
    __syncthreads();
    for (int off = 128; off; off >>= 1) {
        if (threadIdx.x < off) sm[threadIdx.x] += sm[threadIdx.x + off];
        __syncthreads();
    }
    if (threadIdx.x == 0) {
        g_bsum[blockIdx.x] = sm[0];
        __threadfence();
        int t = atomicAdd(&g_arrive, 1);
        lastFlag = (t == gridDim.x - 1);
    }
    __syncthreads();
    if (lastFlag) {
        int t = threadIdx.x;
        int v = (t < NBLK) ? g_bsum[t] : 0;
        sm[t] = v;
        __syncthreads();
        for (int off = 1; off < 256; off <<= 1) {
            int u = (t >= off) ? sm[t - off] : 0;
            __syncthreads();
            sm[t] += u;
            __syncthreads();
        }
        if (t < NBLK) g_bsum[t] = sm[t] - v;
        if (t == NBLK - 1) g_rowptr[NN] = sm[t];
    }
}

// ---------------- (4) per-block exclusive scan -> rowptr, cursor ----------------
__global__ void k_scan3() {
    __shared__ int sm[256];
    int i = blockIdx.x * 256 + threadIdx.x;
    int v = (i < NN) ? g_cnt[i] : 0;
    sm[threadIdx.x] = v;
    __syncthreads();
    for (int off = 1; off < 256; off <<= 1) {
        int u = (threadIdx.x >= off) ? sm[threadIdx.x - off] : 0;
        __syncthreads();
        sm[threadIdx.x] += u;
        __syncthreads();
    }
    if (i < NN) {
        int ex = sm[threadIdx.x] - v + g_bsum[blockIdx.x];
        g_rowptr[i] = ex;
        g_cursor[i] = ex;
    }
}

// ---------------- (5) scatter edges to CSR + prep xc rows ----------------
__global__ void k_scatter_prep(const void* ei, const float* __restrict__ ea,
                               const float* __restrict__ x, const float* __restrict__ sdf,
                               const float* __restrict__ nat) {
    int idx = blockIdx.x * blockDim.x + threadIdx.x;
    if (idx < NE) {
        int e = idx;
        int d = eload(ei, NE + e);
        int s = eload(ei, e);
        int pos = atomicAdd(&g_cursor[d], 1);
        g_src[pos] = s;
        float4 v0 = make_float4(ea[e * 6 + 0], ea[e * 6 + 1], ea[e * 6 + 2], ea[e * 6 + 3]);
        float4 v1 = make_float4(ea[e * 6 + 4], ea[e * 6 + 5], 0.f, 0.f);
        *(float4*)(g_ea + (size_t)pos * 8)     = v0;
        *(float4*)(g_ea + (size_t)pos * 8 + 4) = v1;
    }
    if (idx < NN) {
        float* r = &g_xc[(size_t)idx * XLD];
#pragma unroll
        for (int c = 0; c < 5; c++) r[c] = x[idx * 5 + c];
        r[5] = sdf[idx];
        r[6] = nat[idx];
    }
}

// ---------------- xc concat fixups ----------------
__global__ void k_setcol(int col, const float* __restrict__ src) {
    int n = blockIdx.x * blockDim.x + threadIdx.x;
    if (n < NN) g_xc[(size_t)n * XLD + col] = src[n];
}
__global__ void k_copyfy(const float* __restrict__ fy) {
    int idx = blockIdx.x * blockDim.x + threadIdx.x;
    if (idx >= NN * 3) return;
    int n = idx / 3, c = idx - n * 3;
    g_xc[(size_t)n * XLD + c] = fy[idx];
}

// ---------------- weight prep: fp16, permuted k = h*in_c + i ----------------
__global__ void k_permw_f16(const float* __restrict__ wout, int in_c, int Kpad) {
    int K = 3 * in_c;
    int idx = blockIdx.x * blockDim.x + threadIdx.x;
    if (idx >= 512 * Kpad) return;
    int o = idx / Kpad, k = idx - o * Kpad;
    float v = 0.f;
    if (k < K) {
        int h = k / in_c, i = k - h * in_c;
        v = wout[(size_t)o * K + i * 3 + h];
    }
    g_wh[(size_t)o * AP + k] = __float2half_rn(v);
}

// ---------------- (6) fused scaling + gather + segment-sum -> fp16 ----------------
// Occupancy 3: tail-channel weights (used by threads 0..3 only) moved to SMEM
// so all threads carry only 2 register weight sets (~75 regs).
__global__ void __launch_bounds__(256, 3) k_aggr(int in_c, int kpad,
                                                 const float* __restrict__ win,
                                                 const float* __restrict__ bin) {
    __shared__ float s_ea[ESTG * 8];
    __shared__ int   s_src[ESTG];
    __shared__ float s_wt[4 * 18];
    __shared__ float s_bt[4 * 3];
    const int tid = threadIdx.x;
    const int i0 = tid, i1 = tid + 256, i2 = tid + 512;
    const bool v1 = (i1 < in_c), v2 = (i2 < in_c);

    float w0[18], w1[18];
#pragma unroll
    for (int t = 0; t < 18; t++) {
        w0[t] = (i0 < in_c) ? win[i0 * 18 + t] : 0.f;
        w1[t] = v1 ? win[i1 * 18 + t] : 0.f;
    }
    float b0[3], b1[3];
#pragma unroll
    for (int h = 0; h < 3; h++) {
        b0[h] = (i0 < in_c) ? bin[i0 * 3 + h] : 0.f;
        b1[h] = v1 ? bin[i1 * 3 + h] : 0.f;
    }
    // tail weights -> smem (≤4 channels)
    if (tid < 4 * 18) {
        int c = 512 + tid / 18;
        s_wt[tid] = (c < in_c) ? win[c * 18 + tid % 18] : 0.f;
    }
    if (tid < 4 * 3) {
        int c = 512 + tid / 3;
        s_bt[tid] = (c < in_c) ? bin[c * 3 + tid % 3] : 0.f;
    }

    const int R = 3 * in_c, pad = kpad - R;
    const int n0 = blockIdx.x * 64;
    const int nend = (n0 + 64 < NN) ? n0 + 64 : NN;
    const int e0 = g_rowptr[n0], e1 = g_rowptr[nend];

    float a0[3] = {0.f, 0.f, 0.f}, a1[3] = {0.f, 0.f, 0.f}, a2[3] = {0.f, 0.f, 0.f};
    int n = n0;
    int ws = e0;
    while (true) {
        int wc = e1 - ws;
        if (wc > ESTG) wc = ESTG;
        if (wc < 0) wc = 0;
        __syncthreads();
        for (int t = tid; t < wc * 8; t += 256) s_ea[t] = g_ea[(size_t)ws * 8 + t];
        for (int t = tid; t < wc; t += 256) s_src[t] = g_src[ws + t];
        __syncthreads();
        const int wend = ws + wc;

        while (n < nend) {
            const int rs = g_rowptr[n], re = g_rowptr[n + 1];
            const int js = (rs > ws) ? rs : ws;
            const int je = (re < wend) ? re : wend;
            for (int j = js; j < je; j++) {
                const int lj = j - ws;
                const int s = s_src[lj];
                const float xv0 = __ldg(&g_xc[(size_t)s * XLD + i0]);
                const float xv1 = v1 ? __ldg(&g_xc[(size_t)s * XLD + i1]) : 0.f;
                const float4 ef0 = *(const float4*)&s_ea[lj * 8];
                const float2 ef1 = *(const float2*)&s_ea[lj * 8 + 4];
                const float ev[6] = {ef0.x, ef0.y, ef0.z, ef0.w, ef1.x, ef1.y};
                {
                    float s0 = b0[0], s1 = b0[1], s2 = b0[2];
#pragma unroll
                    for (int a = 0; a < 6; a++) {
                        float e = ev[a];
                        s0 = fmaf(e, w0[a], s0);
                        s1 = fmaf(e, w0[6 + a], s1);
                        s2 = fmaf(e, w0[12 + a], s2);
                    }
                    a0[0] = fmaf(fmaxf(s0, 0.f), xv0, a0[0]);
                    a0[1] = fmaf(fmaxf(s1, 0.f), xv0, a0[1]);
                    a0[2] = fmaf(fmaxf(s2, 0.f), xv0, a0[2]);
                }
                {
                    float s0 = b1[0], s1 = b1[1], s2 = b1[2];
#pragma unroll
                    for (int a = 0; a < 6; a++) {
                        float e = ev[a];
                        s0 = fmaf(e, w1[a], s0);
                        s1 = fmaf(e, w1[6 + a], s1);
                        s2 = fmaf(e, w1[12 + a], s2);
                    }
                    a1[0] = fmaf(fmaxf(s0, 0.f), xv1, a1[0]);
                    a1[1] = fmaf(fmaxf(s1, 0.f), xv1, a1[1]);
                    a1[2] = fmaf(fmaxf(s2, 0.f), xv1, a1[2]);
                }
                if (v2) {   // only threads 0..3 (warp 0); weights read from smem
                    const float xv2 = __ldg(&g_xc[(size_t)s * XLD + i2]);
                    const float* wt = &s_wt[tid * 18];
                    float s0 = s_bt[tid * 3 + 0], s1 = s_bt[tid * 3 + 1], s2 = s_bt[tid * 3 + 2];
#pragma unroll
                    for (int a = 0; a < 6; a++) {
                        float e = ev[a];
                        s0 = fmaf(e, wt[a], s0);
                        s1 = fmaf(e, wt[6 + a], s1);
                        s2 = fmaf(e, wt[12 + a], s2);
                    }
                    a2[0] = fmaf(fmaxf(s0, 0.f), xv2, a2[0]);
                    a2[1] = fmaf(fmaxf(s1, 0.f), xv2, a2[1]);
                    a2[2] = fmaf(fmaxf(s2, 0.f), xv2, a2[2]);
                }
            }
            if (re <= wend) {
                const size_t rb = (size_t)n * AP;
                if (i0 < in_c) {
                    g_ah[rb + i0]            = __float2half_rn(a0[0]);
                    g_ah[rb + in_c + i0]     = __float2half_rn(a0[1]);
                    g_ah[rb + 2 * in_c + i0] = __float2half_rn(a0[2]);
                }
                if (v1) {
                    g_ah[rb + i1]            = __float2half_rn(a1[0]);
                    g_ah[rb + in_c + i1]     = __float2half_rn(a1[1]);
                    g_ah[rb + 2 * in_c + i1] = __float2half_rn(a1[2]);
                }
                if (v2) {
                    g_ah[rb + i2]            = __float2half_rn(a2[0]);
                    g_ah[rb + in_c + i2]     = __float2half_rn(a2[1]);
                    g_ah[rb + 2 * in_c + i2] = __float2half_rn(a2[2]);
                }
                for (int p = tid; p < pad; p += 256)
                    g_ah[rb + R + p] = __float2half_rn(0.f);
#pragma unroll
                for (int q = 0; q < 3; q++) { a0[q] = 0.f; a1[q] = 0.f; a2[q] = 0.f; }
                n++;
            } else {
                break;   // node straddles window; carry acc to next window
            }
        }
        if (n >= nend) break;
        ws += ESTG;
    }
}

// ---------------- fp16 HMMA GEMM, 128x128 tile, K-chunk 64, cp.async 2-stage ----------------
#define SROW  144                 // 128B row + 16B pad (4-bank row offset, conflict-free)
#define SA    0
#define SB    (128 * SROW)        // 18432
#define STGSZ (2 * 128 * SROW)    // 36864
#define SMTOT (2 * STGSZ)         // 73728

__device__ __forceinline__ void gemm_issue(uint32_t st, int c, int tid,
                                           int m0, int n0, int M) {
#pragma unroll
    for (int it = 0; it < 4; it++) {
        int t = tid + it * 256;
        int row = t >> 3, c16 = t & 7;
        int rga = m0 + row; if (rga >= M) rga = M - 1;
        size_t ka = (size_t)c * 64 + c16 * 8;
        uint32_t d = st + row * SROW + c16 * 16;
        cpa16(d + SA, g_ah + (size_t)rga * AP + ka);
        cpa16(d + SB, g_wh + (size_t)(n0 + row) * AP + ka);
    }
    cp_commit();
}

__global__ void __launch_bounds__(256, 2) k_gemm_mma(int M, int NC,
                                                     const float* __restrict__ bias,
                                                     int coloff) {
    extern __shared__ __align__(16) char dsm[];
    const int tid = threadIdx.x;
    const int wid = tid >> 5;
    const int lane = tid & 31;
    const int m0 = blockIdx.y * 128;
    const int n0 = blockIdx.x * 128;
    const uint32_t sb = su32(dsm);

    const int wm = (wid >> 2) * 64;
    const int wn = (wid & 3) * 32;

    float acc[4][4][4];
#pragma unroll
    for (int mt = 0; mt < 4; mt++)
#pragma unroll
        for (int nt = 0; nt < 4; nt++)
#pragma unroll
            for (int q = 0; q < 4; q++) acc[mt][nt][q] = 0.f;

    gemm_issue(sb, 0, tid, m0, n0, M);

    for (int c = 0; c < NC; c++) {
        const int b = c & 1;
        if (c + 1 < NC) {
            gemm_issue(sb + ((c + 1) & 1) * STGSZ, c + 1, tid, m0, n0, M);
            cp_wait<1>();
        } else {
            cp_wait<0>();
        }
        __syncthreads();

        const uint32_t st = sb + b * STGSZ;
#pragma unroll
        for (int s = 0; s < 4; s++) {
            uint32_t ah[4][4];
#pragma unroll
            for (int mt = 0; mt < 4; mt++) {
                uint32_t row = wm + mt * 16 + (lane & 15);
                uint32_t ad = st + SA + row * SROW + s * 32 + (lane >> 4) * 16;
                ldm4(ah[mt], ad);
            }
            uint32_t bh[4][2];
#pragma unroll
            for (int p = 0; p < 2; p++) {
                uint32_t row = wn + p * 16 + (lane & 7) + (lane >> 4) * 8;
                uint32_t bd = st + SB + row * SROW + s * 32 + ((lane >> 3) & 1) * 16;
                uint32_t r[4];
                ldm4(r, bd);
                bh[2 * p][0] = r[0]; bh[2 * p][1] = r[1];
                bh[2 * p + 1][0] = r[2]; bh[2 * p + 1][1] = r[3];
            }
#pragma unroll
            for (int mt = 0; mt < 4; mt++)
#pragma unroll
                for (int nt = 0; nt < 4; nt++)
                    mma16816(acc[mt][nt], ah[mt], bh[nt]);
        }
        __syncthreads();
    }

#pragma unroll
    for (int mt = 0; mt < 4; mt++) {
        int gm0 = m0 + wm + mt * 16 + (lane >> 2);
        int gm1 = gm0 + 8;
#pragma unroll
        for (int nt = 0; nt < 4; nt++) {
            int cn = n0 + wn + nt * 8 + (lane & 3) * 2;
            float b0 = bias[cn], b1 = bias[cn + 1];
            if (gm0 < M) {
                float* p = &g_xc[(size_t)gm0 * XLD + coloff + cn];
                p[0] = fmaxf(ftanh(acc[mt][nt][0] + b0), 0.f);
                p[1] = fmaxf(ftanh(acc[mt][nt][1] + b1), 0.f);
            }
            if (gm1 < M) {
                float* p = &g_xc[(size_t)gm1 * XLD + coloff + cn];
                p[0] = fmaxf(ftanh(acc[mt][nt][2] + b0), 0.f);
                p[1] = fmaxf(ftanh(acc[mt][nt][3] + b1), 0.f);
            }
        }
    }
}

// ---------------- last layer (out_c = 3): warp per node, fp32, tanh only ----------------
__global__ void __launch_bounds__(256) k_gemm_small(int in_c, const float* __restrict__ wout,
                                                    const float* __restrict__ bias,
                                                    float* __restrict__ out) {
    int node = blockIdx.x * 8 + (threadIdx.x >> 5);
    int lane = threadIdx.x & 31;
    if (node >= NN) return;
    const int K = 3 * in_c;
    const __half* hi = g_ah + (size_t)node * AP;
    float c0 = 0.f, c1 = 0.f, c2 = 0.f;
    for (int h = 0; h < 3; h++) {
        for (int i = lane; i < in_c; i += 32) {
            int k = h * in_c + i;
            float a = __half2float(hi[k]);
            int wi = i * 3 + h;
            c0 = fmaf(a, wout[0 * (size_t)K + wi], c0);
            c1 = fmaf(a, wout[1 * (size_t)K + wi], c1);
            c2 = fmaf(a, wout[2 * (size_t)K + wi], c2);
        }
    }
#pragma unroll
    for (int o = 16; o; o >>= 1) {
        c0 += __shfl_down_sync(0xffffffffu, c0, o);
        c1 += __shfl_down_sync(0xffffffffu, c1, o);
        c2 += __shfl_down_sync(0xffffffffu, c2, o);
    }
    if (lane == 0) {
        out[(size_t)node * 3 + 0] = tanhf(c0 + bias[0]);
        out[(size_t)node * 3 + 1] = tanhf(c1 + bias[1]);
        out[(size_t)node * 3 + 2] = tanhf(c2 + bias[2]);
    }
}

// ---------------- launch ----------------
extern "C" void kernel_launch(void* const* d_in, const int* in_sizes, int n_in,
                              void* d_out, int out_size) {
    (void)in_sizes; (void)n_in; (void)out_size;
    const float* x   = (const float*)d_in[0];
    const float* sdf = (const float*)d_in[1];
    const float* nat = (const float*)d_in[2];
    const float* ea  = (const float*)d_in[3];
    const float* fy  = (const float*)d_in[4];
    const void*  ei  = d_in[5];
    const float* win[6];  const float* bin[6];
    const float* wout[6]; const float* bout[6];
    for (int l = 0; l < 6; l++) {
        win[l]  = (const float*)d_in[6 + 4 * l];
        bin[l]  = (const float*)d_in[7 + 4 * l];
        wout[l] = (const float*)d_in[8 + 4 * l];
        bout[l] = (const float*)d_in[9 + 4 * l];
    }
    float* out = (float*)d_out;

    static const int IN_C[6] = {7, 513, 513, 516, 513, 513};
    static const int COFF[6] = {0, 0, 3, 0, 0, 0};

    cudaFuncSetAttribute(k_gemm_mma, cudaFuncAttributeMaxDynamicSharedMemorySize, SMTOT);

    const int TB = 256;
    k_zero_detect<<<(NN + TB - 1) / TB, TB>>>((const int*)ei);
    k_hist<<<(NE + TB - 1) / TB, TB>>>(ei);
    k_scan12<<<NBLK, 256>>>();
    k_scan3<<<NBLK, 256>>>();
    k_scatter_prep<<<(NE + TB - 1) / TB, TB>>>(ei, ea, x, sdf, nat);

    for (int l = 0; l < 6; l++) {
        const int inc = IN_C[l];
        const int K = 3 * inc;
        const int NC = (K + 63) / 64;
        const int Kpad = NC * 64;

        k_aggr<<<(NN + 63) / 64, 256>>>(inc, Kpad, win[l], bin[l]);
        if (l < 5) {
            k_permw_f16<<<(512 * Kpad + TB - 1) / TB, TB>>>(wout[l], inc, Kpad);
            dim3 grid(4, (NN + 127) / 128);
            k_gemm_mma<<<grid, 256, SMTOT>>>(NN, NC, bout[l], COFF[l]);
        } else {
            k_gemm_small<<<(NN + 7) / 8, 256>>>(inc, wout[l], bout[l], out);
        }
        if (l == 0) {
            k_setcol<<<(NN + TB - 1) / TB, TB>>>(512, nat);
        } else if (l == 2) {
            k_copyfy<<<(NN * 3 + TB - 1) / TB, TB>>>(fy);
            k_setcol<<<(NN + TB - 1) / TB, TB>>>(515, nat);
        } else if (l == 3) {
            k_setcol<<<(NN + TB - 1) / TB, TB>>>(512, nat);
        }
    }
}